// round 8
// baseline (speedup 1.0000x reference)
#include <cuda_runtime.h>
#include <cstdint>

#define BATCH 16
#define NPTS  4096
#define CH    64
#define MCENT 1024
#define KNB   32
#define RAD2  0.04f

typedef unsigned long long u64;

// scratch (allocation-free rule: __device__ globals)
__device__ float    g_pf[BATCH * NPTS * 64];   // 16 MB: W1[:,3:]@feat + b1, [b][n][64]
__device__ unsigned g_prog[BATCH];             // FPS progress (centroids published)
__device__ unsigned g_pfdone;                  // pf blocks completed

// packed f32x2 helpers (sm_100+)
#define PK2(out, lo, hi)  asm("mov.b64 %0, {%1, %2};" : "=l"(out) : "f"(lo), "f"(hi))
#define UPK2(lo, hi, in)  asm("mov.b64 {%0, %1}, %2;" : "=f"(lo), "=f"(hi) : "l"(in))
#define ADD2(o, a, b)     asm("add.rn.f32x2 %0, %1, %2;" : "=l"(o) : "l"(a), "l"(b))
#define MUL2(o, a, b)     asm("mul.rn.f32x2 %0, %1, %2;" : "=l"(o) : "l"(a), "l"(b))
#define FMA2(o, a, b, c)  asm("fma.rn.f32x2 %0, %1, %2, %3;" : "=l"(o) : "l"(a), "l"(b), "l"(c))

__device__ __forceinline__ unsigned ldvol(const unsigned* p) {
    unsigned v; asm volatile("ld.volatile.global.u32 %0, [%1];" : "=r"(v) : "l"(p)); return v;
}

// bufA addressing: stride 68 floats/row + XOR swizzle of float4 index by (r>>3)&3
__device__ __forceinline__ int aidx(int r, int c4) {
    return r * 68 + (((c4 ^ (r >> 3)) & 3) << 2) + ((c4 >> 2) << 4);
}

__global__ void init_kernel() {
    int t = threadIdx.x;
    if (t < BATCH) g_prog[t] = 0u;
    if (t == BATCH) g_pfdone = 0u;
}

// ---------------------------------------------------------------------------
// Packed-f32x2 2x8 register-tile GEMM from swizzled bufA + [c][o] weight smem.
// ---------------------------------------------------------------------------
template <int WS>
__device__ __forceinline__ void gemm2x8p(const float* __restrict__ A,
                                         const float* __restrict__ W,
                                         int r0, int o0, int sw, u64 (&acc)[2][4]) {
#pragma unroll
    for (int i = 0; i < 2; i++)
#pragma unroll
        for (int j = 0; j < 4; j++) acc[i][j] = 0ull;

#pragma unroll 2
    for (int cc = 0; cc < 64; cc += 4) {
        const int c4  = cc >> 2;
        const int pc4 = ((c4 >> 2) << 4) + (((c4 ^ sw) & 3) << 2);
        float4 a0 = *(const float4*)(A + r0 * 68 + pc4);
        float4 a1 = *(const float4*)(A + (r0 + 1) * 68 + pc4);
#pragma unroll
        for (int j = 0; j < 4; j++) {
            const float* wrow = W + (cc + j) * WS + o0;
            ulonglong2 wA = *(const ulonglong2*)(wrow);
            ulonglong2 wB = *(const ulonglong2*)(wrow + 4);
            float v0 = (j == 0) ? a0.x : (j == 1) ? a0.y : (j == 2) ? a0.z : a0.w;
            float v1 = (j == 0) ? a1.x : (j == 1) ? a1.y : (j == 2) ? a1.z : a1.w;
            u64 p0, p1; PK2(p0, v0, v0); PK2(p1, v1, v1);
            FMA2(acc[0][0], p0, wA.x, acc[0][0]);
            FMA2(acc[0][1], p0, wA.y, acc[0][1]);
            FMA2(acc[0][2], p0, wB.x, acc[0][2]);
            FMA2(acc[0][3], p0, wB.y, acc[0][3]);
            FMA2(acc[1][0], p1, wA.x, acc[1][0]);
            FMA2(acc[1][1], p1, wA.y, acc[1][1]);
            FMA2(acc[1][2], p1, wB.x, acc[1][2]);
            FMA2(acc[1][3], p1, wB.y, acc[1][3]);
        }
    }
}

// ---------------------------------------------------------------------------
// MEGA kernel: bids [0,16) FPS, [16,144) pf, [144,4240) fused ballq+MLP.
// 512 threads/block; 1 block/SM (smem+regs) -> FPS never shares an SM.
// ---------------------------------------------------------------------------
__global__ void __launch_bounds__(512) mega_kernel(
    const float* __restrict__ pts, const float* __restrict__ feats,
    const float* __restrict__ w1, const float* __restrict__ b1,
    const float* __restrict__ g1, const float* __restrict__ be1,
    const float* __restrict__ w2, const float* __restrict__ b2,
    const float* __restrict__ g2, const float* __restrict__ be2,
    const float* __restrict__ w3, const float* __restrict__ b3,
    const float* __restrict__ g3, const float* __restrict__ be3,
    float* __restrict__ cent_out, float* __restrict__ out) {
    extern __shared__ float sm[];
    const int tid = threadIdx.x;

    if (blockIdx.x < BATCH) {
        // =================== FPS role ===================
        float* spx = sm;
        float* spy = sm + NPTS;
        float* spz = sm + 2 * NPTS;
        unsigned* swd = (unsigned*)(sm + 3 * NPTS);   // [2][16]
        unsigned* swn = swd + 32;

        const int b    = blockIdx.x;
        const int lane = tid & 31;
        const int warp = tid >> 5;
        const float* pb = pts + b * 3 * NPTS;

        float xs[8], ys[8], zs[8], dist[8];
#pragma unroll
        for (int i = 0; i < 8; i++) {
            int n = tid + i * 512;
            xs[i] = pb[n]; ys[i] = pb[NPTS + n]; zs[i] = pb[2 * NPTS + n];
            spx[n] = xs[i]; spy[n] = ys[i]; spz[n] = zs[i];
            dist[i] = 1e10f;
        }
        u64 X[4], Y[4], Z[4];
#pragma unroll
        for (int j = 0; j < 4; j++) {
            PK2(X[j], xs[2 * j], xs[2 * j + 1]);
            PK2(Y[j], ys[2 * j], ys[2 * j + 1]);
            PK2(Z[j], zs[2 * j], zs[2 * j + 1]);
        }
        __syncthreads();

        float cx = spx[0], cy = spy[0], cz = spz[0];
        float* centb = cent_out + b * 3 * MCENT;
        if (tid == 0) { centb[0] = cx; centb[MCENT] = cy; centb[2 * MCENT] = cz; }

        int p = 0;
        for (int m = 1; m < MCENT; m++) {
            float ncx = -cx, ncy = -cy, ncz = -cz;
            u64 ncx2, ncy2, ncz2;
            PK2(ncx2, ncx, ncx); PK2(ncy2, ncy, ncy); PK2(ncz2, ncz, ncz);
#pragma unroll
            for (int j = 0; j < 4; j++) {
                u64 dx, dy, dz, t;
                ADD2(dx, X[j], ncx2);
                MUL2(t, dx, dx);
                ADD2(dy, Y[j], ncy2);
                FMA2(t, dy, dy, t);
                ADD2(dz, Z[j], ncz2);
                FMA2(t, dz, dz, t);
                float lo, hi; UPK2(lo, hi, t);
                dist[2 * j]     = fminf(dist[2 * j], lo);
                dist[2 * j + 1] = fminf(dist[2 * j + 1], hi);
            }
            float bd = dist[0]; int bi = 0;
#pragma unroll
            for (int i = 1; i < 8; i++) if (dist[i] > bd) { bd = dist[i]; bi = i; }
            unsigned bn = (unsigned)(tid + bi * 512);
            unsigned du = __float_as_uint(bd);
            unsigned wm = __reduce_max_sync(0xffffffffu, du);
            unsigned cd = (du == wm) ? bn : 0xffffffffu;
            unsigned wi = __reduce_min_sync(0xffffffffu, cd);
            if (lane == 0) { swd[p * 16 + warp] = wm; swn[p * 16 + warp] = wi; }
            __syncthreads();
            unsigned kd = (lane < 16) ? swd[p * 16 + lane] : 0u;
            unsigned kn = (lane < 16) ? swn[p * 16 + lane] : 0xffffffffu;
            unsigned gm = __reduce_max_sync(0xffffffffu, kd);
            unsigned c2 = (kd == gm) ? kn : 0xffffffffu;
            unsigned n  = __reduce_min_sync(0xffffffffu, c2);
            cx = spx[n]; cy = spy[n]; cz = spz[n];
            if (tid == 0) {
                centb[m] = cx; centb[MCENT + m] = cy; centb[2 * MCENT + m] = cz;
                if ((m & 3) == 3) {          // publish every 4 centroids
                    __threadfence();
                    atomicExch(&g_prog[b], (unsigned)(m + 1));
                }
            }
            p ^= 1;
        }
    } else if (blockIdx.x < BATCH + 128) {
        // =================== pf role ===================
        float* w1s = sm;            // [c][o] 64*64
        float* b1s = sm + 4096;
        for (int i = tid; i < 64 * 64; i += 512) {
            int c = i >> 6, o = i & 63;
            w1s[i] = w1[o * 67 + 3 + c];
        }
        if (tid < 64) b1s[tid] = b1[tid];
        __syncthreads();

        int bi = blockIdx.x - BATCH;          // 0..127
        int b  = bi >> 3;
        int n  = (bi & 7) * 512 + tid;
        const float* fb = feats + b * CH * NPTS + n;

        float acc[64];
#pragma unroll
        for (int o = 0; o < 64; o++) acc[o] = b1s[o];
#pragma unroll 4
        for (int c = 0; c < 64; c++) {
            float f = fb[c * NPTS];
#pragma unroll
            for (int o = 0; o < 64; o += 4) {
                float4 w = *(const float4*)&w1s[(c << 6) + o];
                acc[o]     = fmaf(w.x, f, acc[o]);
                acc[o + 1] = fmaf(w.y, f, acc[o + 1]);
                acc[o + 2] = fmaf(w.z, f, acc[o + 2]);
                acc[o + 3] = fmaf(w.w, f, acc[o + 3]);
            }
        }
        float* dst = g_pf + (b * NPTS + n) * 64;
#pragma unroll
        for (int o = 0; o < 64; o += 4)
            *(float4*)(dst + o) = make_float4(acc[o], acc[o + 1], acc[o + 2], acc[o + 3]);
        __threadfence();
        __syncthreads();
        if (tid == 0) atomicAdd(&g_pfdone, 1u);
    } else {
        // =================== ballq + MLP role ===================
        float* bufA  = sm;                      // 128*68 (swizzled)
        float* w2s   = bufA + 8704;             // [c][o] 64*64
        float* w3s   = w2s + 4096;              // [c][o] 64*128
        float* w1ps  = w3s + 8192;              // [d][o] 3*64
        float* s1    = w1ps + 192;
        float* be1s  = s1 + 64;
        float* b2s   = be1s + 64;
        float* s2    = b2s + 64;
        float* be2s  = s2 + 64;
        float* b3s   = be2s + 64;               // 128
        float* s3    = b3s + 128;
        float* be3s  = s3 + 128;
        float* loc   = be3s + 128;              // [3][128]
        float* centv = loc + 384;               // [4][3] (+pad)
        int*   outb  = (int*)(centv + 16);      // [4][128]
        int*   shits = outb + 512;              // [4][4][32]
        int*   scnt  = shits + 512;             // [4][4]
        int*   sfirst= scnt + 16;               // [4][4]
        int*   ni_s  = sfirst + 16;             // [4][32]

        const int i   = blockIdx.x - BATCH - 128;
        const int b   = i & 15;
        const int m0  = ((i >> 4) & 255) << 2;
        const int lane = tid & 31;
        const int w    = tid >> 5;
        const float rs = rsqrtf(1.0f + 1e-5f);

        // weights first (independent of FPS)
        for (int k = tid; k < 64 * 64; k += 512) { int c = k >> 6, o = k & 63;  w2s[k] = w2[o * 64 + c]; }
        for (int k = tid; k < 64 * 128; k += 512){ int c = k >> 7, o = k & 127; w3s[k] = w3[o * 64 + c]; }
        if (tid < 192) { int d = tid >> 6, o = tid & 63; w1ps[tid] = w1[o * 67 + d]; }
        if (tid < 64) {
            s1[tid] = g1[tid] * rs; be1s[tid] = be1[tid];
            b2s[tid] = b2[tid]; s2[tid] = g2[tid] * rs; be2s[tid] = be2[tid];
        }
        if (tid < 128) { b3s[tid] = b3[tid]; s3[tid] = g3[tid] * rs; be3s[tid] = be3[tid]; }
        outb[tid] = 0;

        // wait for pf + the 4 centroids of this group
        if (tid == 0) {
            while (ldvol(&g_pfdone) < 128u) __nanosleep(128);
            while (ldvol(&g_prog[b]) < (unsigned)(m0 + 4)) __nanosleep(128);
            __threadfence();
        }
        __syncthreads();
        if (tid < 12)   // centroid coords via L2 (L1 may hold a stale line)
            centv[tid] = __ldcg(cent_out + b * 3 * MCENT + (tid % 3) * MCENT + m0 + tid / 3);
        __syncthreads();

        // ball query: warp w -> centroid g = w>>2, segment q = w&3 (1024 pts)
        {
            const int g = w >> 2, q = w & 3;
            const float* pb = pts + b * 3 * NPTS;
            float cx = centv[g * 3], cy = centv[g * 3 + 1], cz = centv[g * 3 + 2];
            float c2 = cx * cx + cy * cy + cz * cz;
            int cnt = 0, first = -1;
            const int base0 = q * 1024;
            for (int base = base0; base < base0 + 1024; base += 32) {
                int n = base + lane;
                float x = pb[n], y = pb[NPTS + n], z = pb[2 * NPTS + n];
                float p2  = x * x + y * y + z * z;
                float dot = cx * x + cy * y + cz * z;
                float d2  = c2 + p2 - 2.f * dot;
                bool hit = (d2 <= RAD2);
                unsigned mask = __ballot_sync(0xffffffffu, hit);
                if (mask) {
                    if (first < 0) first = base + __ffs(mask) - 1;
                    if (hit) {
                        int rank = cnt + __popc(mask & ((1u << lane) - 1u));
                        if (rank < KNB) shits[(g * 4 + q) * 32 + rank] = n;
                    }
                    cnt += __popc(mask);
                    if (cnt >= KNB) break;
                }
            }
            if (lane == 0) {
                scnt[g * 4 + q] = (cnt < KNB) ? cnt : KNB;
                sfirst[g * 4 + q] = first;
            }
        }
        __syncthreads();
        // merge segments in index order (warps 0-3, one per centroid)
        if (w < 4) {
            const int g = w;
            int c0 = scnt[g * 4], c1 = scnt[g * 4 + 1], c2i = scnt[g * 4 + 2], c3 = scnt[g * 4 + 3];
            int off1 = c0, off2 = c0 + c1, off3 = off2 + c2i;
            int total = off3 + c3; if (total > KNB) total = KNB;
            if (lane < c0  && lane        < KNB) ni_s[g * 32 + lane]        = shits[(g * 4 + 0) * 32 + lane];
            if (lane < c1  && off1 + lane < KNB) ni_s[g * 32 + off1 + lane] = shits[(g * 4 + 1) * 32 + lane];
            if (lane < c2i && off2 + lane < KNB) ni_s[g * 32 + off2 + lane] = shits[(g * 4 + 2) * 32 + lane];
            if (lane < c3  && off3 + lane < KNB) ni_s[g * 32 + off3 + lane] = shits[(g * 4 + 3) * 32 + lane];
            __syncwarp();
            int f = (total > 0) ? ni_s[g * 32] : (NPTS - 1);
            if (lane >= total) ni_s[g * 32 + lane] = f;
        }
        __syncthreads();

        // gather: warp w -> group g = w>>2, k-range [q*8, q*8+8)
        {
            const int g = w >> 2, q = w & 3;
            const float* pb = pts + b * 3 * NPTS;
            float cx = centv[g * 3], cy = centv[g * 3 + 1], cz = centv[g * 3 + 2];
#pragma unroll
            for (int k = q * 8; k < q * 8 + 8; k++) {
                int n = ni_s[g * 32 + k];
                int r = g * 32 + k;
                if (lane == 0) {
                    loc[r]       = pb[n] - cx;
                    loc[128 + r] = pb[NPTS + n] - cy;
                    loc[256 + r] = pb[2 * NPTS + n] - cz;
                }
                float2 v = *(const float2*)(g_pf + (b * NPTS + n) * 64 + lane * 2);
                *(float2*)(bufA + aidx(r, lane >> 1) + ((lane & 1) << 1)) = v;
            }
        }
        __syncthreads();

        // layer 1: 4 threads/row, in place in bufA
        {
            const int r = tid >> 2;
            const int oq = (tid & 3) * 16;
            float lx = loc[r], ly = loc[128 + r], lz = loc[256 + r];
#pragma unroll
            for (int o = oq; o < oq + 16; o += 4) {
                float* ap = bufA + aidx(r, o >> 2);
                float4 p  = *(float4*)ap;
                float4 wx = *(const float4*)(w1ps + o);
                float4 wy = *(const float4*)(w1ps + 64 + o);
                float4 wz = *(const float4*)(w1ps + 128 + o);
                float4 sc = *(const float4*)(s1 + o);
                float4 eb = *(const float4*)(be1s + o);
                p.x = fmaf(wz.x, lz, fmaf(wy.x, ly, fmaf(wx.x, lx, p.x)));
                p.y = fmaf(wz.y, lz, fmaf(wy.y, ly, fmaf(wx.y, lx, p.y)));
                p.z = fmaf(wz.z, lz, fmaf(wy.z, ly, fmaf(wx.z, lx, p.z)));
                p.w = fmaf(wz.w, lz, fmaf(wy.w, ly, fmaf(wx.w, lx, p.w)));
                p.x = fmaxf(fmaf(p.x, sc.x, eb.x), 0.f);
                p.y = fmaxf(fmaf(p.y, sc.y, eb.y), 0.f);
                p.z = fmaxf(fmaf(p.z, sc.z, eb.z), 0.f);
                p.w = fmaxf(fmaf(p.w, sc.w, eb.w), 0.f);
                *(float4*)ap = p;
            }
        }
        __syncthreads();

        const int rt = tid >> 3, ct = tid & 7;
        const int r0 = rt * 2, o0 = ct * 8;
        const int sw = (rt >> 2) & 3;

        // layer 2 IN PLACE
        {
            u64 acc[2][4];
            gemm2x8p<64>(bufA, w2s, r0, o0, sw, acc);
            float ac[2][8];
#pragma unroll
            for (int ii = 0; ii < 2; ii++)
#pragma unroll
                for (int j = 0; j < 4; j++) UPK2(ac[ii][2 * j], ac[ii][2 * j + 1], acc[ii][j]);
            float4 bb0 = *(const float4*)(b2s + o0),  bb1 = *(const float4*)(b2s + o0 + 4);
            float4 ss0 = *(const float4*)(s2 + o0),   ss1 = *(const float4*)(s2 + o0 + 4);
            float4 ee0 = *(const float4*)(be2s + o0), ee1 = *(const float4*)(be2s + o0 + 4);
#pragma unroll
            for (int ii = 0; ii < 2; ii++) {
                ac[ii][0] = fmaxf(fmaf(ac[ii][0] + bb0.x, ss0.x, ee0.x), 0.f);
                ac[ii][1] = fmaxf(fmaf(ac[ii][1] + bb0.y, ss0.y, ee0.y), 0.f);
                ac[ii][2] = fmaxf(fmaf(ac[ii][2] + bb0.z, ss0.z, ee0.z), 0.f);
                ac[ii][3] = fmaxf(fmaf(ac[ii][3] + bb0.w, ss0.w, ee0.w), 0.f);
                ac[ii][4] = fmaxf(fmaf(ac[ii][4] + bb1.x, ss1.x, ee1.x), 0.f);
                ac[ii][5] = fmaxf(fmaf(ac[ii][5] + bb1.y, ss1.y, ee1.y), 0.f);
                ac[ii][6] = fmaxf(fmaf(ac[ii][6] + bb1.z, ss1.z, ee1.z), 0.f);
                ac[ii][7] = fmaxf(fmaf(ac[ii][7] + bb1.w, ss1.w, ee1.w), 0.f);
            }
            __syncthreads();   // all gemm reads of bufA complete
            const int c4a = o0 >> 2;
#pragma unroll
            for (int ii = 0; ii < 2; ii++) {
                *(float4*)(bufA + aidx(r0 + ii, c4a)) =
                    make_float4(ac[ii][0], ac[ii][1], ac[ii][2], ac[ii][3]);
                *(float4*)(bufA + aidx(r0 + ii, c4a + 1)) =
                    make_float4(ac[ii][4], ac[ii][5], ac[ii][6], ac[ii][7]);
            }
        }
        __syncthreads();

        // layer 3 (two col passes) + fused maxpool
        const int gg = r0 >> 5;
#pragma unroll 1
        for (int pp = 0; pp < 2; pp++) {
            const int q0 = o0 + pp * 64;
            u64 acc[2][4];
            gemm2x8p<128>(bufA, w3s, r0, q0, sw, acc);
            float ac[2][8];
#pragma unroll
            for (int ii = 0; ii < 2; ii++)
#pragma unroll
                for (int j = 0; j < 4; j++) UPK2(ac[ii][2 * j], ac[ii][2 * j + 1], acc[ii][j]);
            float4 bb0 = *(const float4*)(b3s + q0),  bb1 = *(const float4*)(b3s + q0 + 4);
            float4 ss0 = *(const float4*)(s3 + q0),   ss1 = *(const float4*)(s3 + q0 + 4);
            float4 ee0 = *(const float4*)(be3s + q0), ee1 = *(const float4*)(be3s + q0 + 4);
            float cm[8];
#pragma unroll
            for (int j = 0; j < 8; j++) cm[j] = 0.f;
#pragma unroll
            for (int ii = 0; ii < 2; ii++) {
                cm[0] = fmaxf(cm[0], fmaxf(fmaf(ac[ii][0] + bb0.x, ss0.x, ee0.x), 0.f));
                cm[1] = fmaxf(cm[1], fmaxf(fmaf(ac[ii][1] + bb0.y, ss0.y, ee0.y), 0.f));
                cm[2] = fmaxf(cm[2], fmaxf(fmaf(ac[ii][2] + bb0.z, ss0.z, ee0.z), 0.f));
                cm[3] = fmaxf(cm[3], fmaxf(fmaf(ac[ii][3] + bb0.w, ss0.w, ee0.w), 0.f));
                cm[4] = fmaxf(cm[4], fmaxf(fmaf(ac[ii][4] + bb1.x, ss1.x, ee1.x), 0.f));
                cm[5] = fmaxf(cm[5], fmaxf(fmaf(ac[ii][5] + bb1.y, ss1.y, ee1.y), 0.f));
                cm[6] = fmaxf(cm[6], fmaxf(fmaf(ac[ii][6] + bb1.z, ss1.z, ee1.z), 0.f));
                cm[7] = fmaxf(cm[7], fmaxf(fmaf(ac[ii][7] + bb1.w, ss1.w, ee1.w), 0.f));
            }
#pragma unroll
            for (int j = 0; j < 8; j++)
                atomicMax(&outb[gg * 128 + q0 + j], __float_as_int(cm[j]));
        }
        __syncthreads();

        if (tid < 128) {
            int o = tid;
            float4 v;
            v.x = __int_as_float(outb[0 * 128 + o]);
            v.y = __int_as_float(outb[1 * 128 + o]);
            v.z = __int_as_float(outb[2 * 128 + o]);
            v.w = __int_as_float(outb[3 * 128 + o]);
            *(float4*)(out + (b * 128 + o) * MCENT + m0) = v;
        }
    }
}

// ---------------------------------------------------------------------------
extern "C" void kernel_launch(void* const* d_in, const int* in_sizes, int n_in,
                              void* d_out, int out_size) {
    const float* points   = (const float*)d_in[0];
    const float* features = (const float*)d_in[1];
    const float* w1  = (const float*)d_in[2];
    const float* b1  = (const float*)d_in[3];
    const float* g1  = (const float*)d_in[4];
    const float* be1 = (const float*)d_in[5];
    const float* w2  = (const float*)d_in[6];
    const float* b2  = (const float*)d_in[7];
    const float* g2  = (const float*)d_in[8];
    const float* be2 = (const float*)d_in[9];
    const float* w3  = (const float*)d_in[10];
    const float* b3  = (const float*)d_in[11];
    const float* g3  = (const float*)d_in[12];
    const float* be3 = (const float*)d_in[13];

    float* cent_out = (float*)d_out;                       // [B][3][M]
    float* out      = cent_out + BATCH * 3 * MCENT;        // [B][128][M]

    const int mega_smem = 118784;   // >114KB -> exactly 1 block/SM
    cudaFuncSetAttribute(mega_kernel, cudaFuncAttributeMaxDynamicSharedMemorySize, mega_smem);

    init_kernel<<<1, 32>>>();
    mega_kernel<<<BATCH + 128 + BATCH * (MCENT / 4), 512, mega_smem>>>(
        points, features, w1, b1, g1, be1, w2, b2, g2, be2, w3, b3, g3, be3,
        cent_out, out);
}

// round 9
// speedup vs baseline: 1.3033x; 1.3033x over previous
#include <cuda_runtime.h>
#include <cstdint>

#define BATCH 16
#define NPTS  4096
#define CH    64
#define MCENT 1024
#define KNB   32
#define RAD2  0.04f

typedef unsigned long long u64;

// scratch (allocation-free rule: __device__ globals)
__device__ float g_pf[BATCH * NPTS * 64];        // 16 MB: W1[:,3:]@feat + b1, [b][n][64]
__device__ int   g_nidx[BATCH * MCENT * KNB];    // 2 MB

// packed f32x2 helpers (sm_100+)
#define PK2(out, lo, hi)  asm("mov.b64 %0, {%1, %2};" : "=l"(out) : "f"(lo), "f"(hi))
#define UPK2(lo, hi, in)  asm("mov.b64 {%0, %1}, %2;" : "=f"(lo), "=f"(hi) : "l"(in))
#define ADD2(o, a, b)     asm("add.rn.f32x2 %0, %1, %2;" : "=l"(o) : "l"(a), "l"(b))
#define MUL2(o, a, b)     asm("mul.rn.f32x2 %0, %1, %2;" : "=l"(o) : "l"(a), "l"(b))
#define FMA2(o, a, b, c)  asm("fma.rn.f32x2 %0, %1, %2, %3;" : "=l"(o) : "l"(a), "l"(b), "l"(c))

// bufA addressing: stride 68 floats/row + XOR swizzle of float4 index by (r>>3)&3
__device__ __forceinline__ int aidx(int r, int c4) {
    return r * 68 + (((c4 ^ (r >> 3)) & 3) << 2) + ((c4 >> 2) << 4);
}

// ---------------------------------------------------------------------------
// Kernel 1 (fused): blocks 0..15 do FPS (1 block per batch, 512 thr, 8 pts/thr);
// blocks 16..143 do the pf precompute (hidden under FPS's long tail).
// ---------------------------------------------------------------------------
__global__ void __launch_bounds__(512) fps_pf_kernel(const float* __restrict__ pts,
                                                     const float* __restrict__ feats,
                                                     const float* __restrict__ w1,
                                                     const float* __restrict__ b1,
                                                     float* __restrict__ cent_out) {
    if (blockIdx.x < BATCH) {
        // ----------------- FPS -----------------
        extern __shared__ float fs[];
        float* spx = fs;
        float* spy = fs + NPTS;
        float* spz = fs + 2 * NPTS;
        unsigned* swd = (unsigned*)(fs + 3 * NPTS);          // [2][16]
        unsigned* swn = swd + 32;                            // [2][16]

        const int b    = blockIdx.x;
        const int tid  = threadIdx.x;
        const int lane = tid & 31;
        const int warp = tid >> 5;
        const float* pb = pts + b * 3 * NPTS;

        float xs[8], ys[8], zs[8], dist[8];
#pragma unroll
        for (int i = 0; i < 8; i++) {
            int n = tid + i * 512;
            xs[i] = pb[n]; ys[i] = pb[NPTS + n]; zs[i] = pb[2 * NPTS + n];
            spx[n] = xs[i]; spy[n] = ys[i]; spz[n] = zs[i];
            dist[i] = 1e10f;
        }
        u64 X[4], Y[4], Z[4];
#pragma unroll
        for (int j = 0; j < 4; j++) {
            PK2(X[j], xs[2 * j], xs[2 * j + 1]);
            PK2(Y[j], ys[2 * j], ys[2 * j + 1]);
            PK2(Z[j], zs[2 * j], zs[2 * j + 1]);
        }
        __syncthreads();

        float cx = spx[0], cy = spy[0], cz = spz[0];
        float* centb = cent_out + b * 3 * MCENT;
        if (tid == 0) { centb[0] = cx; centb[MCENT] = cy; centb[2 * MCENT] = cz; }

        int p = 0;
        for (int m = 1; m < MCENT; m++) {
            float ncx = -cx, ncy = -cy, ncz = -cz;
            u64 ncx2, ncy2, ncz2;
            PK2(ncx2, ncx, ncx); PK2(ncy2, ncy, ncy); PK2(ncz2, ncz, ncz);
#pragma unroll
            for (int j = 0; j < 4; j++) {
                u64 dx, dy, dz, t;
                ADD2(dx, X[j], ncx2);
                MUL2(t, dx, dx);
                ADD2(dy, Y[j], ncy2);
                FMA2(t, dy, dy, t);
                ADD2(dz, Z[j], ncz2);
                FMA2(t, dz, dz, t);
                float lo, hi; UPK2(lo, hi, t);
                dist[2 * j]     = fminf(dist[2 * j], lo);
                dist[2 * j + 1] = fminf(dist[2 * j + 1], hi);
            }
            float bd = dist[0]; int bi = 0;
#pragma unroll
            for (int i = 1; i < 8; i++) if (dist[i] > bd) { bd = dist[i]; bi = i; }
            unsigned bn = (unsigned)(tid + bi * 512);
            unsigned du = __float_as_uint(bd);
            unsigned wm = __reduce_max_sync(0xffffffffu, du);
            unsigned cd = (du == wm) ? bn : 0xffffffffu;
            unsigned wi = __reduce_min_sync(0xffffffffu, cd);
            if (lane == 0) { swd[p * 16 + warp] = wm; swn[p * 16 + warp] = wi; }
            __syncthreads();
            unsigned kd = (lane < 16) ? swd[p * 16 + lane] : 0u;
            unsigned kn = (lane < 16) ? swn[p * 16 + lane] : 0xffffffffu;
            unsigned gm = __reduce_max_sync(0xffffffffu, kd);
            unsigned c2 = (kd == gm) ? kn : 0xffffffffu;
            unsigned n  = __reduce_min_sync(0xffffffffu, c2);
            cx = spx[n]; cy = spy[n]; cz = spz[n];
            if (tid == 0) { centb[m] = cx; centb[MCENT + m] = cy; centb[2 * MCENT + m] = cz; }
            p ^= 1;
        }
    } else {
        // ----------------- pf: pf[b][n][o] = b1[o] + W1[:,3:] @ feats[b][:,n] --
        __shared__ float w1s[64][64];   // [c][o]
        __shared__ float b1s[64];
        const int tid = threadIdx.x;
        for (int i = tid; i < 64 * 64; i += 512) {
            int c = i >> 6, o = i & 63;
            w1s[c][o] = w1[o * 67 + 3 + c];
        }
        if (tid < 64) b1s[tid] = b1[tid];
        __syncthreads();

        int bi = blockIdx.x - BATCH;          // 0..127
        int b  = bi >> 3;
        int n  = (bi & 7) * 512 + tid;
        const float* fb = feats + b * CH * NPTS + n;

        float acc[64];
#pragma unroll
        for (int o = 0; o < 64; o++) acc[o] = b1s[o];
#pragma unroll 4
        for (int c = 0; c < 64; c++) {
            float f = fb[c * NPTS];
#pragma unroll
            for (int o = 0; o < 64; o += 4) {
                float4 w = *(const float4*)&w1s[c][o];
                acc[o]     = fmaf(w.x, f, acc[o]);
                acc[o + 1] = fmaf(w.y, f, acc[o + 1]);
                acc[o + 2] = fmaf(w.z, f, acc[o + 2]);
                acc[o + 3] = fmaf(w.w, f, acc[o + 3]);
            }
        }
        float* dst = g_pf + (b * NPTS + n) * 64;
#pragma unroll
        for (int o = 0; o < 64; o += 4)
            *(float4*)(dst + o) = make_float4(acc[o], acc[o + 1], acc[o + 2], acc[o + 3]);
    }
}

// ---------------------------------------------------------------------------
// Kernel 2: ball query. One warp per centroid; ordered ballot scan over N,
// taking the first K (by index) points with d2 <= R^2, padded with first hit.
// ---------------------------------------------------------------------------
__global__ void __launch_bounds__(256) ballq_kernel(const float* __restrict__ pts,
                                                    const float* __restrict__ cent) {
    int gwarp = (blockIdx.x * blockDim.x + threadIdx.x) >> 5;
    int lane  = threadIdx.x & 31;
    if (gwarp >= BATCH * MCENT) return;
    int b = gwarp >> 10, m = gwarp & 1023;
    const float* pb = pts + b * 3 * NPTS;
    const float* cb = cent + b * 3 * MCENT;
    float cx = cb[m], cy = cb[MCENT + m], cz = cb[2 * MCENT + m];
    float c2 = cx * cx + cy * cy + cz * cz;
    int* ni = g_nidx + (b * MCENT + m) * KNB;

    int cnt = 0, first = -1;
    for (int base = 0; base < NPTS; base += 32) {
        int n = base + lane;
        float x = pb[n], y = pb[NPTS + n], z = pb[2 * NPTS + n];
        float p2  = x * x + y * y + z * z;
        float dot = cx * x + cy * y + cz * z;
        float d2  = c2 + p2 - 2.f * dot;
        bool hit = (d2 <= RAD2);
        unsigned mask = __ballot_sync(0xffffffffu, hit);
        if (mask) {
            if (first < 0) first = base + __ffs(mask) - 1;
            if (hit) {
                int rank = cnt + __popc(mask & ((1u << lane) - 1u));
                if (rank < KNB) ni[rank] = n;
            }
            cnt += __popc(mask);
            if (cnt >= KNB) break;
        }
    }
    if (cnt < KNB) {
        int f = (first < 0) ? (NPTS - 1) : first;
        for (int s = cnt + lane; s < KNB; s += 32) ni[s] = f;
    }
}

// ---------------------------------------------------------------------------
// Packed-f32x2 4x8 register-tile GEMM from swizzled bufA + [c][o] weight smem.
// acc[i][j] holds outputs (row r0+i, cols o0+2j, o0+2j+1) packed in f32x2.
// ---------------------------------------------------------------------------
template <int WS>
__device__ __forceinline__ void gemm4x8p(const float* __restrict__ A,
                                         const float* __restrict__ W,
                                         int r0, int o0, int sw, u64 (&acc)[4][4]) {
#pragma unroll
    for (int i = 0; i < 4; i++)
#pragma unroll
        for (int j = 0; j < 4; j++) acc[i][j] = 0ull;

#pragma unroll 2
    for (int cc = 0; cc < 64; cc += 4) {
        const int c4  = cc >> 2;
        const int pc4 = ((c4 >> 2) << 4) + (((c4 ^ sw) & 3) << 2);  // swizzled float offset
        float4 a[4];
#pragma unroll
        for (int i = 0; i < 4; i++)
            a[i] = *(const float4*)(A + (r0 + i) * 68 + pc4);
#pragma unroll
        for (int j = 0; j < 4; j++) {
            const float* wrow = W + (cc + j) * WS + o0;
            ulonglong2 wA = *(const ulonglong2*)(wrow);
            ulonglong2 wB = *(const ulonglong2*)(wrow + 4);
#pragma unroll
            for (int i = 0; i < 4; i++) {
                float av = (j == 0) ? a[i].x : (j == 1) ? a[i].y : (j == 2) ? a[i].z : a[i].w;
                u64 ap; PK2(ap, av, av);
                FMA2(acc[i][0], ap, wA.x, acc[i][0]);
                FMA2(acc[i][1], ap, wA.y, acc[i][1]);
                FMA2(acc[i][2], ap, wB.x, acc[i][2]);
                FMA2(acc[i][3], ap, wB.y, acc[i][3]);
            }
        }
    }
}

// ---------------------------------------------------------------------------
// Kernel 3: fused gather + 3-layer MLP + maxpool. Block = 4 groups (128 rows),
// 256 threads, 4x8 register tiles (low reg pressure, 16 warps/SM @ 2 blk/SM).
// bufA swizzled (conflict-free gemm loads), layer 2 in place.
// ---------------------------------------------------------------------------
__global__ void __launch_bounds__(256) mlp_kernel(
    const float* __restrict__ pts,
    const float* __restrict__ w1, const float* __restrict__ g1, const float* __restrict__ be1,
    const float* __restrict__ w2, const float* __restrict__ b2,
    const float* __restrict__ g2, const float* __restrict__ be2,
    const float* __restrict__ w3, const float* __restrict__ b3,
    const float* __restrict__ g3, const float* __restrict__ be3,
    const float* __restrict__ cent, float* __restrict__ out) {
    extern __shared__ float sm[];
    float* bufA  = sm;                      // 128*68 = 8704 (swizzled)
    float* w2s   = bufA + 128 * 68;         // [c][o] 64*64
    float* w3s   = w2s + 64 * 64;           // [c][o] 64*128
    float* w1ps  = w3s + 64 * 128;          // [d][o] 3*64
    float* s1    = w1ps + 192;
    float* be1s  = s1 + 64;
    float* b2s   = be1s + 64;
    float* s2    = b2s + 64;
    float* be2s  = s2 + 64;
    float* b3s   = be2s + 64;               // 128
    float* s3    = b3s + 128;
    float* be3s  = s3 + 128;
    float* loc   = be3s + 128;              // [3][128]
    float* centv = loc + 384;               // [4][3] (+pad)
    int*   outb  = (int*)(centv + 16);      // [4][128]

    const int tid = threadIdx.x;
    const int bId = blockIdx.x;
    const int b   = bId >> 8;
    const int m0  = (bId & 255) << 2;
    const float rs = rsqrtf(1.0f + 1e-5f);

    for (int i = tid; i < 64 * 64; i += 256) { int c = i >> 6, o = i & 63;  w2s[i] = w2[o * 64 + c]; }
    for (int i = tid; i < 64 * 128; i += 256){ int c = i >> 7, o = i & 127; w3s[i] = w3[o * 67 - o * 3 + c]; }
    if (tid < 192) { int d = tid >> 6, o = tid & 63; w1ps[tid] = w1[o * 67 + d]; }
    if (tid < 64) {
        s1[tid] = g1[tid] * rs; be1s[tid] = be1[tid];
        b2s[tid] = b2[tid]; s2[tid] = g2[tid] * rs; be2s[tid] = be2[tid];
    }
    if (tid < 128) { b3s[tid] = b3[tid]; s3[tid] = g3[tid] * rs; be3s[tid] = be3[tid]; }
    for (int i = tid; i < 512; i += 256) outb[i] = 0;
    if (tid < 12) centv[tid] = cent[b * 3 * MCENT + (tid % 3) * MCENT + m0 + tid / 3];
    __syncthreads();

    // gather: warp w (0..7) -> group g = w>>1, k-range [q*16, q*16+16)
    {
        const int w = tid >> 5, lane = tid & 31;
        const int g = w >> 1, q = w & 1;
        const int m = m0 + g;
        const int* ni = g_nidx + (b * MCENT + m) * KNB;
        const float* pb = pts + b * 3 * NPTS;
        float cx = centv[g * 3], cy = centv[g * 3 + 1], cz = centv[g * 3 + 2];
        int nk = (lane < 16) ? ni[q * 16 + lane] : 0;
#pragma unroll 4
        for (int k = 0; k < 16; k++) {
            int n = __shfl_sync(0xffffffffu, nk, k);
            int r = g * 32 + q * 16 + k;
            if (lane == 0) {
                loc[r]       = pb[n] - cx;
                loc[128 + r] = pb[NPTS + n] - cy;
                loc[256 + r] = pb[2 * NPTS + n] - cz;
            }
            float2 v = *(const float2*)(g_pf + (b * NPTS + n) * 64 + lane * 2);
            *(float2*)(bufA + aidx(r, lane >> 1) + ((lane & 1) << 1)) = v;
        }
    }
    __syncthreads();

    // layer 1: 2 threads/row (32 cols each), in place in bufA
    {
        const int r  = tid >> 1;
        const int oq = (tid & 1) * 32;
        float lx = loc[r], ly = loc[128 + r], lz = loc[256 + r];
#pragma unroll
        for (int o = oq; o < oq + 32; o += 4) {
            float* ap = bufA + aidx(r, o >> 2);
            float4 p  = *(float4*)ap;
            float4 wx = *(const float4*)(w1ps + o);
            float4 wy = *(const float4*)(w1ps + 64 + o);
            float4 wz = *(const float4*)(w1ps + 128 + o);
            float4 sc = *(const float4*)(s1 + o);
            float4 eb = *(const float4*)(be1s + o);
            p.x = fmaf(wz.x, lz, fmaf(wy.x, ly, fmaf(wx.x, lx, p.x)));
            p.y = fmaf(wz.y, lz, fmaf(wy.y, ly, fmaf(wx.y, lx, p.y)));
            p.z = fmaf(wz.z, lz, fmaf(wy.z, ly, fmaf(wx.z, lx, p.z)));
            p.w = fmaf(wz.w, lz, fmaf(wy.w, ly, fmaf(wx.w, lx, p.w)));
            p.x = fmaxf(fmaf(p.x, sc.x, eb.x), 0.f);
            p.y = fmaxf(fmaf(p.y, sc.y, eb.y), 0.f);
            p.z = fmaxf(fmaf(p.z, sc.z, eb.z), 0.f);
            p.w = fmaxf(fmaf(p.w, sc.w, eb.w), 0.f);
            *(float4*)ap = p;
        }
    }
    __syncthreads();

    const int rt = tid >> 3, ct = tid & 7;     // rt 0..31, ct 0..7
    const int r0 = rt * 4, o0 = ct * 8;
    const int sw = (rt >> 1) & 3;              // rows 4rt..4rt+3 share (r>>3)=rt>>1

    // layer 2 IN PLACE: packed acc; sync (all reads done); store; sync
    {
        u64 acc[4][4];
        gemm4x8p<64>(bufA, w2s, r0, o0, sw, acc);
        float ac[4][8];
#pragma unroll
        for (int i = 0; i < 4; i++)
#pragma unroll
            for (int j = 0; j < 4; j++) UPK2(ac[i][2 * j], ac[i][2 * j + 1], acc[i][j]);
        float4 bb0 = *(const float4*)(b2s + o0),  bb1 = *(const float4*)(b2s + o0 + 4);
        float4 ss0 = *(const float4*)(s2 + o0),   ss1 = *(const float4*)(s2 + o0 + 4);
        float4 ee0 = *(const float4*)(be2s + o0), ee1 = *(const float4*)(be2s + o0 + 4);
#pragma unroll
        for (int i = 0; i < 4; i++) {
            ac[i][0] = fmaxf(fmaf(ac[i][0] + bb0.x, ss0.x, ee0.x), 0.f);
            ac[i][1] = fmaxf(fmaf(ac[i][1] + bb0.y, ss0.y, ee0.y), 0.f);
            ac[i][2] = fmaxf(fmaf(ac[i][2] + bb0.z, ss0.z, ee0.z), 0.f);
            ac[i][3] = fmaxf(fmaf(ac[i][3] + bb0.w, ss0.w, ee0.w), 0.f);
            ac[i][4] = fmaxf(fmaf(ac[i][4] + bb1.x, ss1.x, ee1.x), 0.f);
            ac[i][5] = fmaxf(fmaf(ac[i][5] + bb1.y, ss1.y, ee1.y), 0.f);
            ac[i][6] = fmaxf(fmaf(ac[i][6] + bb1.z, ss1.z, ee1.z), 0.f);
            ac[i][7] = fmaxf(fmaf(ac[i][7] + bb1.w, ss1.w, ee1.w), 0.f);
        }
        __syncthreads();   // all gemm reads of bufA complete
        const int c4a = o0 >> 2;
#pragma unroll
        for (int i = 0; i < 4; i++) {
            *(float4*)(bufA + aidx(r0 + i, c4a)) =
                make_float4(ac[i][0], ac[i][1], ac[i][2], ac[i][3]);
            *(float4*)(bufA + aidx(r0 + i, c4a + 1)) =
                make_float4(ac[i][4], ac[i][5], ac[i][6], ac[i][7]);
        }
    }
    __syncthreads();

    // layer 3 (two col passes) + fused maxpool over K into outb
    const int gg = r0 >> 5;
#pragma unroll 1
    for (int p = 0; p < 2; p++) {
        const int q0 = o0 + p * 64;
        u64 acc[4][4];
        gemm4x8p<128>(bufA, w3s, r0, q0, sw, acc);
        float ac[4][8];
#pragma unroll
        for (int i = 0; i < 4; i++)
#pragma unroll
            for (int j = 0; j < 4; j++) UPK2(ac[i][2 * j], ac[i][2 * j + 1], acc[i][j]);
        float4 bb0 = *(const float4*)(b3s + q0),  bb1 = *(const float4*)(b3s + q0 + 4);
        float4 ss0 = *(const float4*)(s3 + q0),   ss1 = *(const float4*)(s3 + q0 + 4);
        float4 ee0 = *(const float4*)(be3s + q0), ee1 = *(const float4*)(be3s + q0 + 4);
        float cm[8];
#pragma unroll
        for (int j = 0; j < 8; j++) cm[j] = 0.f;
#pragma unroll
        for (int i = 0; i < 4; i++) {
            cm[0] = fmaxf(cm[0], fmaxf(fmaf(ac[i][0] + bb0.x, ss0.x, ee0.x), 0.f));
            cm[1] = fmaxf(cm[1], fmaxf(fmaf(ac[i][1] + bb0.y, ss0.y, ee0.y), 0.f));
            cm[2] = fmaxf(cm[2], fmaxf(fmaf(ac[i][2] + bb0.z, ss0.z, ee0.z), 0.f));
            cm[3] = fmaxf(cm[3], fmaxf(fmaf(ac[i][3] + bb0.w, ss0.w, ee0.w), 0.f));
            cm[4] = fmaxf(cm[4], fmaxf(fmaf(ac[i][4] + bb1.x, ss1.x, ee1.x), 0.f));
            cm[5] = fmaxf(cm[5], fmaxf(fmaf(ac[i][5] + bb1.y, ss1.y, ee1.y), 0.f));
            cm[6] = fmaxf(cm[6], fmaxf(fmaf(ac[i][6] + bb1.z, ss1.z, ee1.z), 0.f));
            cm[7] = fmaxf(cm[7], fmaxf(fmaf(ac[i][7] + bb1.w, ss1.w, ee1.w), 0.f));
        }
#pragma unroll
        for (int j = 0; j < 8; j++)
            atomicMax(&outb[gg * 128 + q0 + j], __float_as_int(cm[j]));
    }
    __syncthreads();

    // write out[b][o][m0..m0+3] as one float4 per thread
    if (tid < 128) {
        int o = tid;
        float4 v;
        v.x = __int_as_float(outb[0 * 128 + o]);
        v.y = __int_as_float(outb[1 * 128 + o]);
        v.z = __int_as_float(outb[2 * 128 + o]);
        v.w = __int_as_float(outb[3 * 128 + o]);
        *(float4*)(out + (b * 128 + o) * MCENT + m0) = v;
    }
}

// ---------------------------------------------------------------------------
extern "C" void kernel_launch(void* const* d_in, const int* in_sizes, int n_in,
                              void* d_out, int out_size) {
    const float* points   = (const float*)d_in[0];
    const float* features = (const float*)d_in[1];
    const float* w1  = (const float*)d_in[2];
    const float* b1  = (const float*)d_in[3];
    const float* g1  = (const float*)d_in[4];
    const float* be1 = (const float*)d_in[5];
    const float* w2  = (const float*)d_in[6];
    const float* b2  = (const float*)d_in[7];
    const float* g2  = (const float*)d_in[8];
    const float* be2 = (const float*)d_in[9];
    const float* w3  = (const float*)d_in[10];
    const float* b3  = (const float*)d_in[11];
    const float* g3  = (const float*)d_in[12];
    const float* be3 = (const float*)d_in[13];

    float* cent_out = (float*)d_out;                       // [B][3][M]
    float* out      = cent_out + BATCH * 3 * MCENT;        // [B][128][M]

    const int fps_smem = 3 * NPTS * 4 + 64 * 4;            // pts + 2x[2][16] keys
    const int mlp_smem = 22992 * 4;                        // 91,968 B -> 2 blocks/SM
    cudaFuncSetAttribute(fps_pf_kernel, cudaFuncAttributeMaxDynamicSharedMemorySize, fps_smem);
    cudaFuncSetAttribute(mlp_kernel, cudaFuncAttributeMaxDynamicSharedMemorySize, mlp_smem);

    fps_pf_kernel<<<BATCH + BATCH * 8, 512, fps_smem>>>(points, features, w1, b1, cent_out);
    ballq_kernel<<<(BATCH * MCENT * 32) / 256, 256>>>(points, cent_out);
    mlp_kernel<<<BATCH * (MCENT / 4), 256, mlp_smem>>>(
        points, w1, g1, be1, w2, b2, g2, be2, w3, b3, g3, be3, cent_out, out);
}

// round 10
// speedup vs baseline: 1.5384x; 1.1804x over previous
#include <cuda_runtime.h>
#include <cstdint>

#define BATCH 16
#define NPTS  4096
#define CH    64
#define MCENT 1024
#define KNB   32
#define RAD2  0.04f

typedef unsigned long long u64;

// scratch (allocation-free rule: __device__ globals)
__device__ float g_pf[BATCH * NPTS * 64];        // 16 MB: W1[:,3:]@feat + b1, [b][n][64]
__device__ int   g_nidx[BATCH * MCENT * KNB];    // 2 MB

// packed f32x2 helpers (sm_100+)
#define PK2(out, lo, hi)  asm("mov.b64 %0, {%1, %2};" : "=l"(out) : "f"(lo), "f"(hi))
#define UPK2(lo, hi, in)  asm("mov.b64 {%0, %1}, %2;" : "=f"(lo), "=f"(hi) : "l"(in))
#define ADD2(o, a, b)     asm("add.rn.f32x2 %0, %1, %2;" : "=l"(o) : "l"(a), "l"(b))
#define MUL2(o, a, b)     asm("mul.rn.f32x2 %0, %1, %2;" : "=l"(o) : "l"(a), "l"(b))
#define FMA2(o, a, b, c)  asm("fma.rn.f32x2 %0, %1, %2, %3;" : "=l"(o) : "l"(a), "l"(b), "l"(c))

// bufA addressing: stride 68 floats/row + XOR swizzle of float4 index by (r>>3)&3
__device__ __forceinline__ int aidx(int r, int c4) {
    return r * 68 + (((c4 ^ (r >> 3)) & 3) << 2) + ((c4 >> 2) << 4);
}

// ---------------------------------------------------------------------------
// Kernel 1 (fused, 1024 threads): blocks 0..15 FPS (4 pts/thread);
// blocks 16..143 pf precompute (2 threads/point, 32 channels each) hidden
// under FPS's long tail. __launch_bounds__(1024) caps regs at 64 (no spills:
// FPS role ~40 regs, pf role ~45 regs).
// ---------------------------------------------------------------------------
__global__ void __launch_bounds__(1024) fps_pf_kernel(const float* __restrict__ pts,
                                                      const float* __restrict__ feats,
                                                      const float* __restrict__ w1,
                                                      const float* __restrict__ b1,
                                                      float* __restrict__ cent_out) {
    if (blockIdx.x < BATCH) {
        // ----------------- FPS: 1024 threads, 4 pts/thread -----------------
        extern __shared__ float fs[];
        float* spx = fs;
        float* spy = fs + NPTS;
        float* spz = fs + 2 * NPTS;
        unsigned* swd = (unsigned*)(fs + 3 * NPTS);          // [2][32]
        unsigned* swn = swd + 64;                            // [2][32]

        const int b    = blockIdx.x;
        const int tid  = threadIdx.x;
        const int lane = tid & 31;
        const int warp = tid >> 5;
        const float* pb = pts + b * 3 * NPTS;

        float xs[4], ys[4], zs[4], dist[4];
#pragma unroll
        for (int i = 0; i < 4; i++) {
            int n = tid + i * 1024;
            xs[i] = pb[n]; ys[i] = pb[NPTS + n]; zs[i] = pb[2 * NPTS + n];
            spx[n] = xs[i]; spy[n] = ys[i]; spz[n] = zs[i];
            dist[i] = 1e10f;
        }
        u64 X[2], Y[2], Z[2];
#pragma unroll
        for (int j = 0; j < 2; j++) {
            PK2(X[j], xs[2 * j], xs[2 * j + 1]);
            PK2(Y[j], ys[2 * j], ys[2 * j + 1]);
            PK2(Z[j], zs[2 * j], zs[2 * j + 1]);
        }
        __syncthreads();

        float cx = spx[0], cy = spy[0], cz = spz[0];
        float* centb = cent_out + b * 3 * MCENT;
        if (tid == 0) { centb[0] = cx; centb[MCENT] = cy; centb[2 * MCENT] = cz; }

        int p = 0;
        for (int m = 1; m < MCENT; m++) {
            float ncx = -cx, ncy = -cy, ncz = -cz;
            u64 ncx2, ncy2, ncz2;
            PK2(ncx2, ncx, ncx); PK2(ncy2, ncy, ncy); PK2(ncz2, ncz, ncz);
#pragma unroll
            for (int j = 0; j < 2; j++) {
                u64 dx, dy, dz, t;
                ADD2(dx, X[j], ncx2);
                MUL2(t, dx, dx);
                ADD2(dy, Y[j], ncy2);
                FMA2(t, dy, dy, t);
                ADD2(dz, Z[j], ncz2);
                FMA2(t, dz, dz, t);
                float lo, hi; UPK2(lo, hi, t);
                dist[2 * j]     = fminf(dist[2 * j], lo);
                dist[2 * j + 1] = fminf(dist[2 * j + 1], hi);
            }
            // per-thread argmax (ascending local index; strict > keeps earliest)
            float bd = dist[0]; int bi = 0;
#pragma unroll
            for (int i = 1; i < 4; i++) if (dist[i] > bd) { bd = dist[i]; bi = i; }
            unsigned bn = (unsigned)(tid + bi * 1024);
            // warp reduce: max dist-bits, then min index among exact ties
            unsigned du = __float_as_uint(bd);
            unsigned wm = __reduce_max_sync(0xffffffffu, du);
            unsigned cd = (du == wm) ? bn : 0xffffffffu;
            unsigned wi = __reduce_min_sync(0xffffffffu, cd);
            if (lane == 0) { swd[p * 32 + warp] = wm; swn[p * 32 + warp] = wi; }
            __syncthreads();
            // every warp reduces the 32 per-warp keys (no 2nd barrier needed)
            unsigned kd = swd[p * 32 + lane];
            unsigned kn = swn[p * 32 + lane];
            unsigned gm = __reduce_max_sync(0xffffffffu, kd);
            unsigned c2 = (kd == gm) ? kn : 0xffffffffu;
            unsigned n  = __reduce_min_sync(0xffffffffu, c2);
            cx = spx[n]; cy = spy[n]; cz = spz[n];
            if (tid == 0) { centb[m] = cx; centb[MCENT + m] = cy; centb[2 * MCENT + m] = cz; }
            p ^= 1;
        }
    } else {
        // ------- pf: 2 threads per point, 32 output channels each ----------
        __shared__ float w1s[64][64];   // [c][o]
        __shared__ float b1s[64];
        const int tid = threadIdx.x;
        for (int i = tid; i < 64 * 64; i += 1024) {
            int c = i >> 6, o = i & 63;
            w1s[c][o] = w1[o * 67 + 3 + c];
        }
        if (tid < 64) b1s[tid] = b1[tid];
        __syncthreads();

        int bi = blockIdx.x - BATCH;              // 0..127 (8 blocks per batch)
        int b  = bi >> 3;
        int n  = (bi & 7) * 512 + (tid >> 1);     // 512 points per block
        int oh = (tid & 1) * 32;                  // channel half
        const float* fb = feats + b * CH * NPTS + n;

        float acc[32];
#pragma unroll
        for (int o = 0; o < 32; o++) acc[o] = b1s[oh + o];
#pragma unroll 4
        for (int c = 0; c < 64; c++) {
            float f = fb[c * NPTS];
#pragma unroll
            for (int o = 0; o < 32; o += 4) {
                float4 w = *(const float4*)&w1s[c][oh + o];
                acc[o]     = fmaf(w.x, f, acc[o]);
                acc[o + 1] = fmaf(w.y, f, acc[o + 1]);
                acc[o + 2] = fmaf(w.z, f, acc[o + 2]);
                acc[o + 3] = fmaf(w.w, f, acc[o + 3]);
            }
        }
        float* dst = g_pf + (b * NPTS + n) * 64 + oh;
#pragma unroll
        for (int o = 0; o < 32; o += 4)
            *(float4*)(dst + o) = make_float4(acc[o], acc[o + 1], acc[o + 2], acc[o + 3]);
    }
}

// ---------------------------------------------------------------------------
// Kernel 2: ball query. One warp per centroid; ordered ballot scan over N,
// taking the first K (by index) points with d2 <= R^2, padded with first hit.
// ---------------------------------------------------------------------------
__global__ void __launch_bounds__(256) ballq_kernel(const float* __restrict__ pts,
                                                    const float* __restrict__ cent) {
    int gwarp = (blockIdx.x * blockDim.x + threadIdx.x) >> 5;
    int lane  = threadIdx.x & 31;
    if (gwarp >= BATCH * MCENT) return;
    int b = gwarp >> 10, m = gwarp & 1023;
    const float* pb = pts + b * 3 * NPTS;
    const float* cb = cent + b * 3 * MCENT;
    float cx = cb[m], cy = cb[MCENT + m], cz = cb[2 * MCENT + m];
    float c2 = cx * cx + cy * cy + cz * cz;
    int* ni = g_nidx + (b * MCENT + m) * KNB;

    int cnt = 0, first = -1;
    for (int base = 0; base < NPTS; base += 32) {
        int n = base + lane;
        float x = pb[n], y = pb[NPTS + n], z = pb[2 * NPTS + n];
        float p2  = x * x + y * y + z * z;
        float dot = cx * x + cy * y + cz * z;
        float d2  = c2 + p2 - 2.f * dot;
        bool hit = (d2 <= RAD2);
        unsigned mask = __ballot_sync(0xffffffffu, hit);
        if (mask) {
            if (first < 0) first = base + __ffs(mask) - 1;
            if (hit) {
                int rank = cnt + __popc(mask & ((1u << lane) - 1u));
                if (rank < KNB) ni[rank] = n;
            }
            cnt += __popc(mask);
            if (cnt >= KNB) break;
        }
    }
    if (cnt < KNB) {
        int f = (first < 0) ? (NPTS - 1) : first;
        for (int s = cnt + lane; s < KNB; s += 32) ni[s] = f;
    }
}

// ---------------------------------------------------------------------------
// Packed-f32x2 8x8 register-tile GEMM from swizzled bufA + [c][o] weight smem.
// acc[i][j] holds outputs (row r0+i, cols o0+2j, o0+2j+1) packed in f32x2.
// ---------------------------------------------------------------------------
template <int WS>
__device__ __forceinline__ void gemm8x8p(const float* __restrict__ A,
                                         const float* __restrict__ W,
                                         int r0, int o0, int sw, u64 (&acc)[8][4]) {
#pragma unroll
    for (int i = 0; i < 8; i++)
#pragma unroll
        for (int j = 0; j < 4; j++) acc[i][j] = 0ull;

#pragma unroll 2
    for (int cc = 0; cc < 64; cc += 4) {
        const int c4  = cc >> 2;
        const int pc4 = ((c4 >> 2) << 4) + (((c4 ^ sw) & 3) << 2);  // swizzled float offset
        float4 a[8];
#pragma unroll
        for (int i = 0; i < 8; i++)
            a[i] = *(const float4*)(A + (r0 + i) * 68 + pc4);
#pragma unroll
        for (int j = 0; j < 4; j++) {
            const float* wrow = W + (cc + j) * WS + o0;
            ulonglong2 wA = *(const ulonglong2*)(wrow);
            ulonglong2 wB = *(const ulonglong2*)(wrow + 4);
#pragma unroll
            for (int i = 0; i < 8; i++) {
                float av = (j == 0) ? a[i].x : (j == 1) ? a[i].y : (j == 2) ? a[i].z : a[i].w;
                u64 ap; PK2(ap, av, av);
                FMA2(acc[i][0], ap, wA.x, acc[i][0]);
                FMA2(acc[i][1], ap, wA.y, acc[i][1]);
                FMA2(acc[i][2], ap, wB.x, acc[i][2]);
                FMA2(acc[i][3], ap, wB.y, acc[i][3]);
            }
        }
    }
}

// ---------------------------------------------------------------------------
// Kernel 3: fused gather + 3-layer MLP + maxpool. Block = 4 groups (128 rows),
// 128 threads, 8x8 register tiles (R6 configuration — best measured).
// bufA swizzled (conflict-free gemm loads), layer 2 in place.
// ---------------------------------------------------------------------------
__global__ void __launch_bounds__(128) mlp_kernel(
    const float* __restrict__ pts,
    const float* __restrict__ w1, const float* __restrict__ g1, const float* __restrict__ be1,
    const float* __restrict__ w2, const float* __restrict__ b2,
    const float* __restrict__ g2, const float* __restrict__ be2,
    const float* __restrict__ w3, const float* __restrict__ b3,
    const float* __restrict__ g3, const float* __restrict__ be3,
    const float* __restrict__ cent, float* __restrict__ out) {
    extern __shared__ float sm[];
    float* bufA  = sm;                      // 128*68 = 8704 (swizzled)
    float* w2s   = bufA + 128 * 68;         // [c][o] 64*64
    float* w3s   = w2s + 64 * 64;           // [c][o] 64*128
    float* w1ps  = w3s + 64 * 128;          // [d][o] 3*64
    float* s1    = w1ps + 192;
    float* be1s  = s1 + 64;
    float* b2s   = be1s + 64;
    float* s2    = b2s + 64;
    float* be2s  = s2 + 64;
    float* b3s   = be2s + 64;               // 128
    float* s3    = b3s + 128;
    float* be3s  = s3 + 128;
    float* loc   = be3s + 128;              // [3][128]
    float* centv = loc + 384;               // [4][3] (+pad)
    int*   outb  = (int*)(centv + 16);      // [4][128]

    const int tid = threadIdx.x;
    const int bId = blockIdx.x;
    const int b   = bId >> 8;
    const int m0  = (bId & 255) << 2;
    const float rs = rsqrtf(1.0f + 1e-5f);

    for (int i = tid; i < 64 * 64; i += 128) { int c = i >> 6, o = i & 63;  w2s[i] = w2[o * 64 + c]; }
    for (int i = tid; i < 64 * 128; i += 128){ int c = i >> 7, o = i & 127; w3s[i] = w3[o * 64 + c]; }
    for (int i = tid; i < 192; i += 128)     { int d = i >> 6, o = i & 63;  w1ps[i] = w1[o * 67 + d]; }
    if (tid < 64) {
        s1[tid] = g1[tid] * rs; be1s[tid] = be1[tid];
        b2s[tid] = b2[tid]; s2[tid] = g2[tid] * rs; be2s[tid] = be2[tid];
    }
    if (tid < 128) { b3s[tid] = b3[tid]; s3[tid] = g3[tid] * rs; be3s[tid] = be3[tid]; }
    for (int i = tid; i < 512; i += 128) outb[i] = 0;
    if (tid < 12) centv[tid] = cent[b * 3 * MCENT + (tid % 3) * MCENT + m0 + tid / 3];
    __syncthreads();

    // gather: warp w handles group w (32 rows); writes swizzled float2s
    {
        const int w = tid >> 5, lane = tid & 31;
        const int m = m0 + w;
        const int* ni = g_nidx + (b * MCENT + m) * KNB;
        const float* pb = pts + b * 3 * NPTS;
        float cx = centv[w * 3], cy = centv[w * 3 + 1], cz = centv[w * 3 + 2];
        int nk = ni[lane];
#pragma unroll 4
        for (int k = 0; k < KNB; k++) {
            int n = __shfl_sync(0xffffffffu, nk, k);
            int r = w * 32 + k;
            if (lane == 0) {
                loc[r]       = pb[n] - cx;
                loc[128 + r] = pb[NPTS + n] - cy;
                loc[256 + r] = pb[2 * NPTS + n] - cz;
            }
            float2 v = *(const float2*)(g_pf + (b * NPTS + n) * 64 + lane * 2);
            *(float2*)(bufA + aidx(r, lane >> 1) + ((lane & 1) << 1)) = v;
        }
    }
    __syncthreads();

    // layer 1: y1 = relu((pf + W1p@local) * s1 + be1), in place in bufA
    {
        const int r = tid;
        float lx = loc[r], ly = loc[128 + r], lz = loc[256 + r];
#pragma unroll
        for (int o = 0; o < 64; o += 4) {
            float* ap = bufA + aidx(r, o >> 2);
            float4 p  = *(float4*)ap;
            float4 wx = *(const float4*)(w1ps + o);
            float4 wy = *(const float4*)(w1ps + 64 + o);
            float4 wz = *(const float4*)(w1ps + 128 + o);
            float4 sc = *(const float4*)(s1 + o);
            float4 eb = *(const float4*)(be1s + o);
            p.x = fmaf(wz.x, lz, fmaf(wy.x, ly, fmaf(wx.x, lx, p.x)));
            p.y = fmaf(wz.y, lz, fmaf(wy.y, ly, fmaf(wx.y, lx, p.y)));
            p.z = fmaf(wz.z, lz, fmaf(wy.z, ly, fmaf(wx.z, lx, p.z)));
            p.w = fmaf(wz.w, lz, fmaf(wy.w, ly, fmaf(wx.w, lx, p.w)));
            p.x = fmaxf(fmaf(p.x, sc.x, eb.x), 0.f);
            p.y = fmaxf(fmaf(p.y, sc.y, eb.y), 0.f);
            p.z = fmaxf(fmaf(p.z, sc.z, eb.z), 0.f);
            p.w = fmaxf(fmaf(p.w, sc.w, eb.w), 0.f);
            *(float4*)ap = p;
        }
    }
    __syncthreads();

    const int rt = tid >> 3, ct = tid & 7;
    const int r0 = rt * 8, o0 = ct * 8;
    const int sw = rt & 3;

    // layer 2 IN PLACE: packed acc; sync (all reads done); store; sync
    {
        u64 acc[8][4];
        gemm8x8p<64>(bufA, w2s, r0, o0, sw, acc);
        float ac[8][8];
#pragma unroll
        for (int i = 0; i < 8; i++)
#pragma unroll
            for (int j = 0; j < 4; j++) UPK2(ac[i][2 * j], ac[i][2 * j + 1], acc[i][j]);
        float4 bb0 = *(const float4*)(b2s + o0),  bb1 = *(const float4*)(b2s + o0 + 4);
        float4 ss0 = *(const float4*)(s2 + o0),   ss1 = *(const float4*)(s2 + o0 + 4);
        float4 ee0 = *(const float4*)(be2s + o0), ee1 = *(const float4*)(be2s + o0 + 4);
#pragma unroll
        for (int i = 0; i < 8; i++) {
            ac[i][0] = fmaxf(fmaf(ac[i][0] + bb0.x, ss0.x, ee0.x), 0.f);
            ac[i][1] = fmaxf(fmaf(ac[i][1] + bb0.y, ss0.y, ee0.y), 0.f);
            ac[i][2] = fmaxf(fmaf(ac[i][2] + bb0.z, ss0.z, ee0.z), 0.f);
            ac[i][3] = fmaxf(fmaf(ac[i][3] + bb0.w, ss0.w, ee0.w), 0.f);
            ac[i][4] = fmaxf(fmaf(ac[i][4] + bb1.x, ss1.x, ee1.x), 0.f);
            ac[i][5] = fmaxf(fmaf(ac[i][5] + bb1.y, ss1.y, ee1.y), 0.f);
            ac[i][6] = fmaxf(fmaf(ac[i][6] + bb1.z, ss1.z, ee1.z), 0.f);
            ac[i][7] = fmaxf(fmaf(ac[i][7] + bb1.w, ss1.w, ee1.w), 0.f);
        }
        __syncthreads();   // all gemm reads of bufA complete
        const int c4a = o0 >> 2;
#pragma unroll
        for (int i = 0; i < 8; i++) {
            *(float4*)(bufA + aidx(r0 + i, c4a)) =
                make_float4(ac[i][0], ac[i][1], ac[i][2], ac[i][3]);
            *(float4*)(bufA + aidx(r0 + i, c4a + 1)) =
                make_float4(ac[i][4], ac[i][5], ac[i][6], ac[i][7]);
        }
    }
    __syncthreads();

    // layer 3 (two col passes) + fused maxpool over K into outb
    const int gg = r0 >> 5;
#pragma unroll 1
    for (int p = 0; p < 2; p++) {
        const int q0 = o0 + p * 64;
        u64 acc[8][4];
        gemm8x8p<128>(bufA, w3s, r0, q0, sw, acc);
        float ac[8][8];
#pragma unroll
        for (int i = 0; i < 8; i++)
#pragma unroll
            for (int j = 0; j < 4; j++) UPK2(ac[i][2 * j], ac[i][2 * j + 1], acc[i][j]);
        float4 bb0 = *(const float4*)(b3s + q0),  bb1 = *(const float4*)(b3s + q0 + 4);
        float4 ss0 = *(const float4*)(s3 + q0),   ss1 = *(const float4*)(s3 + q0 + 4);
        float4 ee0 = *(const float4*)(be3s + q0), ee1 = *(const float4*)(be3s + q0 + 4);
        float cm[8];
#pragma unroll
        for (int j = 0; j < 8; j++) cm[j] = 0.f;
#pragma unroll
        for (int i = 0; i < 8; i++) {
            cm[0] = fmaxf(cm[0], fmaxf(fmaf(ac[i][0] + bb0.x, ss0.x, ee0.x), 0.f));
            cm[1] = fmaxf(cm[1], fmaxf(fmaf(ac[i][1] + bb0.y, ss0.y, ee0.y), 0.f));
            cm[2] = fmaxf(cm[2], fmaxf(fmaf(ac[i][2] + bb0.z, ss0.z, ee0.z), 0.f));
            cm[3] = fmaxf(cm[3], fmaxf(fmaf(ac[i][3] + bb0.w, ss0.w, ee0.w), 0.f));
            cm[4] = fmaxf(cm[4], fmaxf(fmaf(ac[i][4] + bb1.x, ss1.x, ee1.x), 0.f));
            cm[5] = fmaxf(cm[5], fmaxf(fmaf(ac[i][5] + bb1.y, ss1.y, ee1.y), 0.f));
            cm[6] = fmaxf(cm[6], fmaxf(fmaf(ac[i][6] + bb1.z, ss1.z, ee1.z), 0.f));
            cm[7] = fmaxf(cm[7], fmaxf(fmaf(ac[i][7] + bb1.w, ss1.w, ee1.w), 0.f));
        }
#pragma unroll
        for (int j = 0; j < 8; j++)
            atomicMax(&outb[gg * 128 + q0 + j], __float_as_int(cm[j]));
    }
    __syncthreads();

    // write out[b][o][m0..m0+3] as one float4 per thread
    {
        int o = tid;
        float4 v;
        v.x = __int_as_float(outb[0 * 128 + o]);
        v.y = __int_as_float(outb[1 * 128 + o]);
        v.z = __int_as_float(outb[2 * 128 + o]);
        v.w = __int_as_float(outb[3 * 128 + o]);
        *(float4*)(out + (b * 128 + o) * MCENT + m0) = v;
    }
}

// ---------------------------------------------------------------------------
extern "C" void kernel_launch(void* const* d_in, const int* in_sizes, int n_in,
                              void* d_out, int out_size) {
    const float* points   = (const float*)d_in[0];
    const float* features = (const float*)d_in[1];
    const float* w1  = (const float*)d_in[2];
    const float* b1  = (const float*)d_in[3];
    const float* g1  = (const float*)d_in[4];
    const float* be1 = (const float*)d_in[5];
    const float* w2  = (const float*)d_in[6];
    const float* b2  = (const float*)d_in[7];
    const float* g2  = (const float*)d_in[8];
    const float* be2 = (const float*)d_in[9];
    const float* w3  = (const float*)d_in[10];
    const float* b3  = (const float*)d_in[11];
    const float* g3  = (const float*)d_in[12];
    const float* be3 = (const float*)d_in[13];

    float* cent_out = (float*)d_out;                       // [B][3][M]
    float* out      = cent_out + BATCH * 3 * MCENT;        // [B][128][M]

    const int fps_smem = 3 * NPTS * 4 + 128 * 4;           // pts + 2x[2][32] keys
    const int mlp_smem = 22992 * 4;                        // 91,968 B -> 2 blocks/SM
    cudaFuncSetAttribute(fps_pf_kernel, cudaFuncAttributeMaxDynamicSharedMemorySize, fps_smem);
    cudaFuncSetAttribute(mlp_kernel, cudaFuncAttributeMaxDynamicSharedMemorySize, mlp_smem);

    fps_pf_kernel<<<BATCH + 128, 1024, fps_smem>>>(points, features, w1, b1, cent_out);
    ballq_kernel<<<(BATCH * MCENT * 32) / 256, 256>>>(points, cent_out);
    mlp_kernel<<<BATCH * (MCENT / 4), 128, mlp_smem>>>(
        points, w1, g1, be1, w2, b2, g2, be2, w3, b3, g3, be3, cent_out, out);
}

// round 11
// speedup vs baseline: 1.6196x; 1.0528x over previous
#include <cuda_runtime.h>
#include <cstdint>

#define BATCH 16
#define NPTS  4096
#define CH    64
#define MCENT 1024
#define KNB   32
#define RAD2  0.04f

typedef unsigned long long u64;

// scratch (allocation-free rule: __device__ globals)
__device__ float g_pf[BATCH * NPTS * 64];        // 16 MB: W1[:,3:]@feat + b1, [b][n][64]
__device__ int   g_nidx[BATCH * MCENT * KNB];    // 2 MB

// packed f32x2 helpers (sm_100+)
#define PK2(out, lo, hi)  asm("mov.b64 %0, {%1, %2};" : "=l"(out) : "f"(lo), "f"(hi))
#define UPK2(lo, hi, in)  asm("mov.b64 {%0, %1}, %2;" : "=f"(lo), "=f"(hi) : "l"(in))
#define ADD2(o, a, b)     asm("add.rn.f32x2 %0, %1, %2;" : "=l"(o) : "l"(a), "l"(b))
#define MUL2(o, a, b)     asm("mul.rn.f32x2 %0, %1, %2;" : "=l"(o) : "l"(a), "l"(b))
#define FMA2(o, a, b, c)  asm("fma.rn.f32x2 %0, %1, %2, %3;" : "=l"(o) : "l"(a), "l"(b), "l"(c))

// bufA addressing: stride 68 floats/row + XOR swizzle of float4 index by (r>>3)&3
__device__ __forceinline__ int aidx(int r, int c4) {
    return r * 68 + (((c4 ^ (r >> 3)) & 3) << 2) + ((c4 >> 2) << 4);
}

// ---------------------------------------------------------------------------
// Kernel 1 (fused): blocks 0..15 do FPS (1 block per batch, 512 thr, 8 pts/thr);
// blocks 16..143 do the pf precompute (hidden under FPS's long tail).
// (R6 configuration — measured best at 314us.)
// ---------------------------------------------------------------------------
__global__ void __launch_bounds__(512) fps_pf_kernel(const float* __restrict__ pts,
                                                     const float* __restrict__ feats,
                                                     const float* __restrict__ w1,
                                                     const float* __restrict__ b1,
                                                     float* __restrict__ cent_out) {
    if (blockIdx.x < BATCH) {
        // ----------------- FPS -----------------
        extern __shared__ float fs[];
        float* spx = fs;
        float* spy = fs + NPTS;
        float* spz = fs + 2 * NPTS;
        unsigned* swd = (unsigned*)(fs + 3 * NPTS);          // [2][16]
        unsigned* swn = swd + 32;                            // [2][16]

        const int b    = blockIdx.x;
        const int tid  = threadIdx.x;
        const int lane = tid & 31;
        const int warp = tid >> 5;
        const float* pb = pts + b * 3 * NPTS;

        float xs[8], ys[8], zs[8], dist[8];
#pragma unroll
        for (int i = 0; i < 8; i++) {
            int n = tid + i * 512;
            xs[i] = pb[n]; ys[i] = pb[NPTS + n]; zs[i] = pb[2 * NPTS + n];
            spx[n] = xs[i]; spy[n] = ys[i]; spz[n] = zs[i];
            dist[i] = 1e10f;
        }
        u64 X[4], Y[4], Z[4];
#pragma unroll
        for (int j = 0; j < 4; j++) {
            PK2(X[j], xs[2 * j], xs[2 * j + 1]);
            PK2(Y[j], ys[2 * j], ys[2 * j + 1]);
            PK2(Z[j], zs[2 * j], zs[2 * j + 1]);
        }
        __syncthreads();

        float cx = spx[0], cy = spy[0], cz = spz[0];
        float* centb = cent_out + b * 3 * MCENT;
        if (tid == 0) { centb[0] = cx; centb[MCENT] = cy; centb[2 * MCENT] = cz; }

        int p = 0;
        for (int m = 1; m < MCENT; m++) {
            float ncx = -cx, ncy = -cy, ncz = -cz;
            u64 ncx2, ncy2, ncz2;
            PK2(ncx2, ncx, ncx); PK2(ncy2, ncy, ncy); PK2(ncz2, ncz, ncz);
#pragma unroll
            for (int j = 0; j < 4; j++) {
                u64 dx, dy, dz, t;
                ADD2(dx, X[j], ncx2);
                MUL2(t, dx, dx);
                ADD2(dy, Y[j], ncy2);
                FMA2(t, dy, dy, t);
                ADD2(dz, Z[j], ncz2);
                FMA2(t, dz, dz, t);
                float lo, hi; UPK2(lo, hi, t);
                dist[2 * j]     = fminf(dist[2 * j], lo);
                dist[2 * j + 1] = fminf(dist[2 * j + 1], hi);
            }
            float bd = dist[0]; int bi = 0;
#pragma unroll
            for (int i = 1; i < 8; i++) if (dist[i] > bd) { bd = dist[i]; bi = i; }
            unsigned bn = (unsigned)(tid + bi * 512);
            unsigned du = __float_as_uint(bd);
            unsigned wm = __reduce_max_sync(0xffffffffu, du);
            unsigned cd = (du == wm) ? bn : 0xffffffffu;
            unsigned wi = __reduce_min_sync(0xffffffffu, cd);
            if (lane == 0) { swd[p * 16 + warp] = wm; swn[p * 16 + warp] = wi; }
            __syncthreads();
            unsigned kd = (lane < 16) ? swd[p * 16 + lane] : 0u;
            unsigned kn = (lane < 16) ? swn[p * 16 + lane] : 0xffffffffu;
            unsigned gm = __reduce_max_sync(0xffffffffu, kd);
            unsigned c2 = (kd == gm) ? kn : 0xffffffffu;
            unsigned n  = __reduce_min_sync(0xffffffffu, c2);
            cx = spx[n]; cy = spy[n]; cz = spz[n];
            if (tid == 0) { centb[m] = cx; centb[MCENT + m] = cy; centb[2 * MCENT + m] = cz; }
            p ^= 1;
        }
    } else {
        // ----------------- pf: pf[b][n][o] = b1[o] + W1[:,3:] @ feats[b][:,n] --
        __shared__ float w1s[64][64];   // [c][o]
        __shared__ float b1s[64];
        const int tid = threadIdx.x;
        for (int i = tid; i < 64 * 64; i += 512) {
            int c = i >> 6, o = i & 63;
            w1s[c][o] = w1[o * 67 + 3 + c];
        }
        if (tid < 64) b1s[tid] = b1[tid];
        __syncthreads();

        int bi = blockIdx.x - BATCH;          // 0..127
        int b  = bi >> 3;
        int n  = (bi & 7) * 512 + tid;
        const float* fb = feats + b * CH * NPTS + n;

        float acc[64];
#pragma unroll
        for (int o = 0; o < 64; o++) acc[o] = b1s[o];
#pragma unroll 4
        for (int c = 0; c < 64; c++) {
            float f = fb[c * NPTS];
#pragma unroll
            for (int o = 0; o < 64; o += 4) {
                float4 w = *(const float4*)&w1s[c][o];
                acc[o]     = fmaf(w.x, f, acc[o]);
                acc[o + 1] = fmaf(w.y, f, acc[o + 1]);
                acc[o + 2] = fmaf(w.z, f, acc[o + 2]);
                acc[o + 3] = fmaf(w.w, f, acc[o + 3]);
            }
        }
        float* dst = g_pf + (b * NPTS + n) * 64;
#pragma unroll
        for (int o = 0; o < 64; o += 4)
            *(float4*)(dst + o) = make_float4(acc[o], acc[o + 1], acc[o + 2], acc[o + 3]);
    }
}

// ---------------------------------------------------------------------------
// Kernel 2: ball query. One warp per centroid; ordered ballot scan over N,
// taking the first K (by index) points with d2 <= R^2, padded with first hit.
// ---------------------------------------------------------------------------
__global__ void __launch_bounds__(256) ballq_kernel(const float* __restrict__ pts,
                                                    const float* __restrict__ cent) {
    int gwarp = (blockIdx.x * blockDim.x + threadIdx.x) >> 5;
    int lane  = threadIdx.x & 31;
    if (gwarp >= BATCH * MCENT) return;
    int b = gwarp >> 10, m = gwarp & 1023;
    const float* pb = pts + b * 3 * NPTS;
    const float* cb = cent + b * 3 * MCENT;
    float cx = cb[m], cy = cb[MCENT + m], cz = cb[2 * MCENT + m];
    float c2 = cx * cx + cy * cy + cz * cz;
    int* ni = g_nidx + (b * MCENT + m) * KNB;

    int cnt = 0, first = -1;
    for (int base = 0; base < NPTS; base += 32) {
        int n = base + lane;
        float x = pb[n], y = pb[NPTS + n], z = pb[2 * NPTS + n];
        float p2  = x * x + y * y + z * z;
        float dot = cx * x + cy * y + cz * z;
        float d2  = c2 + p2 - 2.f * dot;
        bool hit = (d2 <= RAD2);
        unsigned mask = __ballot_sync(0xffffffffu, hit);
        if (mask) {
            if (first < 0) first = base + __ffs(mask) - 1;
            if (hit) {
                int rank = cnt + __popc(mask & ((1u << lane) - 1u));
                if (rank < KNB) ni[rank] = n;
            }
            cnt += __popc(mask);
            if (cnt >= KNB) break;
        }
    }
    if (cnt < KNB) {
        int f = (first < 0) ? (NPTS - 1) : first;
        for (int s = cnt + lane; s < KNB; s += 32) ni[s] = f;
    }
}

// ---------------------------------------------------------------------------
// Packed-f32x2 8x8 register-tile GEMM from swizzled bufA + [c][o] weight smem.
// acc[i][j] holds outputs (row r0+i, cols o0+2j, o0+2j+1) packed in f32x2.
// ---------------------------------------------------------------------------
template <int WS>
__device__ __forceinline__ void gemm8x8p(const float* __restrict__ A,
                                         const float* __restrict__ W,
                                         int r0, int o0, int sw, u64 (&acc)[8][4]) {
#pragma unroll
    for (int i = 0; i < 8; i++)
#pragma unroll
        for (int j = 0; j < 4; j++) acc[i][j] = 0ull;

#pragma unroll 2
    for (int cc = 0; cc < 64; cc += 4) {
        const int c4  = cc >> 2;
        const int pc4 = ((c4 >> 2) << 4) + (((c4 ^ sw) & 3) << 2);  // swizzled float offset
        float4 a[8];
#pragma unroll
        for (int i = 0; i < 8; i++)
            a[i] = *(const float4*)(A + (r0 + i) * 68 + pc4);
#pragma unroll
        for (int j = 0; j < 4; j++) {
            const float* wrow = W + (cc + j) * WS + o0;
            ulonglong2 wA = *(const ulonglong2*)(wrow);
            ulonglong2 wB = *(const ulonglong2*)(wrow + 4);
#pragma unroll
            for (int i = 0; i < 8; i++) {
                float av = (j == 0) ? a[i].x : (j == 1) ? a[i].y : (j == 2) ? a[i].z : a[i].w;
                u64 ap; PK2(ap, av, av);
                FMA2(acc[i][0], ap, wA.x, acc[i][0]);
                FMA2(acc[i][1], ap, wA.y, acc[i][1]);
                FMA2(acc[i][2], ap, wB.x, acc[i][2]);
                FMA2(acc[i][3], ap, wB.y, acc[i][3]);
            }
        }
    }
}

// ---------------------------------------------------------------------------
// Kernel 3: fused gather + 3-layer MLP + maxpool. Block = 4 groups (128 rows),
// 128 threads, 8x8 register tiles. W3 is staged in TWO 16KB half-buffers
// (one per layer-3 column pass) -> smem 74.8KB -> 3 blocks/SM (12 warps).
// ---------------------------------------------------------------------------
__global__ void __launch_bounds__(128) mlp_kernel(
    const float* __restrict__ pts,
    const float* __restrict__ w1, const float* __restrict__ g1, const float* __restrict__ be1,
    const float* __restrict__ w2, const float* __restrict__ b2,
    const float* __restrict__ g2, const float* __restrict__ be2,
    const float* __restrict__ w3, const float* __restrict__ b3,
    const float* __restrict__ g3, const float* __restrict__ be3,
    const float* __restrict__ cent, float* __restrict__ out) {
    extern __shared__ float sm[];
    float* bufA  = sm;                      // 128*68 = 8704 (swizzled)
    float* w2s   = bufA + 8704;             // [c][o] 64*64
    float* w3h   = w2s + 4096;              // [c][oh] 64*64 (active half of W3)
    float* w1ps  = w3h + 4096;              // [d][o] 3*64
    float* s1    = w1ps + 192;
    float* be1s  = s1 + 64;
    float* b2s   = be1s + 64;
    float* s2    = b2s + 64;
    float* be2s  = s2 + 64;
    float* b3s   = be2s + 64;               // 128
    float* s3    = b3s + 128;
    float* be3s  = s3 + 128;
    float* loc   = be3s + 128;              // [3][128]
    float* centv = loc + 384;               // [4][3] (+pad)
    int*   outb  = (int*)(centv + 16);      // [4][128]

    const int tid = threadIdx.x;
    const int bId = blockIdx.x;
    const int b   = bId >> 8;
    const int m0  = (bId & 255) << 2;
    const float rs = rsqrtf(1.0f + 1e-5f);

    for (int i = tid; i < 64 * 64; i += 128) { int c = i >> 6, o = i & 63;  w2s[i] = w2[o * 64 + c]; }
    for (int i = tid; i < 192; i += 128)     { int d = i >> 6, o = i & 63;  w1ps[i] = w1[o * 67 + d]; }
    if (tid < 64) {
        s1[tid] = g1[tid] * rs; be1s[tid] = be1[tid];
        b2s[tid] = b2[tid]; s2[tid] = g2[tid] * rs; be2s[tid] = be2[tid];
    }
    if (tid < 128) { b3s[tid] = b3[tid]; s3[tid] = g3[tid] * rs; be3s[tid] = be3[tid]; }
    for (int i = tid; i < 512; i += 128) outb[i] = 0;
    if (tid < 12) centv[tid] = cent[b * 3 * MCENT + (tid % 3) * MCENT + m0 + tid / 3];
    __syncthreads();

    // gather: warp w handles group w (32 rows); writes swizzled float2s
    {
        const int w = tid >> 5, lane = tid & 31;
        const int m = m0 + w;
        const int* ni = g_nidx + (b * MCENT + m) * KNB;
        const float* pb = pts + b * 3 * NPTS;
        float cx = centv[w * 3], cy = centv[w * 3 + 1], cz = centv[w * 3 + 2];
        int nk = ni[lane];
#pragma unroll 4
        for (int k = 0; k < KNB; k++) {
            int n = __shfl_sync(0xffffffffu, nk, k);
            int r = w * 32 + k;
            if (lane == 0) {
                loc[r]       = pb[n] - cx;
                loc[128 + r] = pb[NPTS + n] - cy;
                loc[256 + r] = pb[2 * NPTS + n] - cz;
            }
            float2 v = *(const float2*)(g_pf + (b * NPTS + n) * 64 + lane * 2);
            *(float2*)(bufA + aidx(r, lane >> 1) + ((lane & 1) << 1)) = v;
        }
    }
    __syncthreads();

    // layer 1: y1 = relu((pf + W1p@local) * s1 + be1), in place in bufA
    {
        const int r = tid;
        float lx = loc[r], ly = loc[128 + r], lz = loc[256 + r];
#pragma unroll
        for (int o = 0; o < 64; o += 4) {
            float* ap = bufA + aidx(r, o >> 2);
            float4 p  = *(float4*)ap;
            float4 wx = *(const float4*)(w1ps + o);
            float4 wy = *(const float4*)(w1ps + 64 + o);
            float4 wz = *(const float4*)(w1ps + 128 + o);
            float4 sc = *(const float4*)(s1 + o);
            float4 eb = *(const float4*)(be1s + o);
            p.x = fmaf(wz.x, lz, fmaf(wy.x, ly, fmaf(wx.x, lx, p.x)));
            p.y = fmaf(wz.y, lz, fmaf(wy.y, ly, fmaf(wx.y, lx, p.y)));
            p.z = fmaf(wz.z, lz, fmaf(wy.z, ly, fmaf(wx.z, lx, p.z)));
            p.w = fmaf(wz.w, lz, fmaf(wy.w, ly, fmaf(wx.w, lx, p.w)));
            p.x = fmaxf(fmaf(p.x, sc.x, eb.x), 0.f);
            p.y = fmaxf(fmaf(p.y, sc.y, eb.y), 0.f);
            p.z = fmaxf(fmaf(p.z, sc.z, eb.z), 0.f);
            p.w = fmaxf(fmaf(p.w, sc.w, eb.w), 0.f);
            *(float4*)ap = p;
        }
    }
    __syncthreads();

    const int rt = tid >> 3, ct = tid & 7;
    const int r0 = rt * 8, o0 = ct * 8;
    const int sw = rt & 3;

    // layer 2 IN PLACE: packed acc; sync (all reads done); store; sync
    {
        u64 acc[8][4];
        gemm8x8p<64>(bufA, w2s, r0, o0, sw, acc);
        float ac[8][8];
#pragma unroll
        for (int i = 0; i < 8; i++)
#pragma unroll
            for (int j = 0; j < 4; j++) UPK2(ac[i][2 * j], ac[i][2 * j + 1], acc[i][j]);
        float4 bb0 = *(const float4*)(b2s + o0),  bb1 = *(const float4*)(b2s + o0 + 4);
        float4 ss0 = *(const float4*)(s2 + o0),   ss1 = *(const float4*)(s2 + o0 + 4);
        float4 ee0 = *(const float4*)(be2s + o0), ee1 = *(const float4*)(be2s + o0 + 4);
#pragma unroll
        for (int i = 0; i < 8; i++) {
            ac[i][0] = fmaxf(fmaf(ac[i][0] + bb0.x, ss0.x, ee0.x), 0.f);
            ac[i][1] = fmaxf(fmaf(ac[i][1] + bb0.y, ss0.y, ee0.y), 0.f);
            ac[i][2] = fmaxf(fmaf(ac[i][2] + bb0.z, ss0.z, ee0.z), 0.f);
            ac[i][3] = fmaxf(fmaf(ac[i][3] + bb0.w, ss0.w, ee0.w), 0.f);
            ac[i][4] = fmaxf(fmaf(ac[i][4] + bb1.x, ss1.x, ee1.x), 0.f);
            ac[i][5] = fmaxf(fmaf(ac[i][5] + bb1.y, ss1.y, ee1.y), 0.f);
            ac[i][6] = fmaxf(fmaf(ac[i][6] + bb1.z, ss1.z, ee1.z), 0.f);
            ac[i][7] = fmaxf(fmaf(ac[i][7] + bb1.w, ss1.w, ee1.w), 0.f);
        }
        __syncthreads();   // all gemm reads of bufA complete
        const int c4a = o0 >> 2;
#pragma unroll
        for (int i = 0; i < 8; i++) {
            *(float4*)(bufA + aidx(r0 + i, c4a)) =
                make_float4(ac[i][0], ac[i][1], ac[i][2], ac[i][3]);
            *(float4*)(bufA + aidx(r0 + i, c4a + 1)) =
                make_float4(ac[i][4], ac[i][5], ac[i][6], ac[i][7]);
        }
    }
    __syncthreads();

    // layer 3: two column passes, each staging its 64-col half of W3 in w3h.
    const int gg = r0 >> 5;
#pragma unroll 1
    for (int p = 0; p < 2; p++) {
        // load half: w3h[c*64 + oh] = w3[(p*64+oh)*64 + c]
        for (int i = tid; i < 4096; i += 128) {
            int c = i >> 6, oh = i & 63;
            w3h[i] = w3[(p * 64 + oh) * 64 + c];
        }
        __syncthreads();

        const int q0 = o0 + p * 64;            // global output column base
        u64 acc[8][4];
        gemm8x8p<64>(bufA, w3h, r0, o0, sw, acc);   // o0 within the half
        float ac[8][8];
#pragma unroll
        for (int i = 0; i < 8; i++)
#pragma unroll
            for (int j = 0; j < 4; j++) UPK2(ac[i][2 * j], ac[i][2 * j + 1], acc[i][j]);
        float4 bb0 = *(const float4*)(b3s + q0),  bb1 = *(const float4*)(b3s + q0 + 4);
        float4 ss0 = *(const float4*)(s3 + q0),   ss1 = *(const float4*)(s3 + q0 + 4);
        float4 ee0 = *(const float4*)(be3s + q0), ee1 = *(const float4*)(be3s + q0 + 4);
        float cm[8];
#pragma unroll
        for (int j = 0; j < 8; j++) cm[j] = 0.f;
#pragma unroll
        for (int i = 0; i < 8; i++) {
            cm[0] = fmaxf(cm[0], fmaxf(fmaf(ac[i][0] + bb0.x, ss0.x, ee0.x), 0.f));
            cm[1] = fmaxf(cm[1], fmaxf(fmaf(ac[i][1] + bb0.y, ss0.y, ee0.y), 0.f));
            cm[2] = fmaxf(cm[2], fmaxf(fmaf(ac[i][2] + bb0.z, ss0.z, ee0.z), 0.f));
            cm[3] = fmaxf(cm[3], fmaxf(fmaf(ac[i][3] + bb0.w, ss0.w, ee0.w), 0.f));
            cm[4] = fmaxf(cm[4], fmaxf(fmaf(ac[i][4] + bb1.x, ss1.x, ee1.x), 0.f));
            cm[5] = fmaxf(cm[5], fmaxf(fmaf(ac[i][5] + bb1.y, ss1.y, ee1.y), 0.f));
            cm[6] = fmaxf(cm[6], fmaxf(fmaf(ac[i][6] + bb1.z, ss1.z, ee1.z), 0.f));
            cm[7] = fmaxf(cm[7], fmaxf(fmaf(ac[i][7] + bb1.w, ss1.w, ee1.w), 0.f));
        }
#pragma unroll
        for (int j = 0; j < 8; j++)
            atomicMax(&outb[gg * 128 + q0 + j], __float_as_int(cm[j]));
        __syncthreads();   // atomics done before w3h reload / output read
    }

    // write out[b][o][m0..m0+3] as one float4 per thread
    {
        int o = tid;
        float4 v;
        v.x = __int_as_float(outb[0 * 128 + o]);
        v.y = __int_as_float(outb[1 * 128 + o]);
        v.z = __int_as_float(outb[2 * 128 + o]);
        v.w = __int_as_float(outb[3 * 128 + o]);
        *(float4*)(out + (b * 128 + o) * MCENT + m0) = v;
    }
}

// ---------------------------------------------------------------------------
extern "C" void kernel_launch(void* const* d_in, const int* in_sizes, int n_in,
                              void* d_out, int out_size) {
    const float* points   = (const float*)d_in[0];
    const float* features = (const float*)d_in[1];
    const float* w1  = (const float*)d_in[2];
    const float* b1  = (const float*)d_in[3];
    const float* g1  = (const float*)d_in[4];
    const float* be1 = (const float*)d_in[5];
    const float* w2  = (const float*)d_in[6];
    const float* b2  = (const float*)d_in[7];
    const float* g2  = (const float*)d_in[8];
    const float* be2 = (const float*)d_in[9];
    const float* w3  = (const float*)d_in[10];
    const float* b3  = (const float*)d_in[11];
    const float* g3  = (const float*)d_in[12];
    const float* be3 = (const float*)d_in[13];

    float* cent_out = (float*)d_out;                       // [B][3][M]
    float* out      = cent_out + BATCH * 3 * MCENT;        // [B][128][M]

    const int fps_smem = 3 * NPTS * 4 + 64 * 4;            // pts + 2x[2][16] keys
    const int mlp_smem = 18704 * 4;                        // 74,816 B -> 3 blocks/SM
    cudaFuncSetAttribute(fps_pf_kernel, cudaFuncAttributeMaxDynamicSharedMemorySize, fps_smem);
    cudaFuncSetAttribute(mlp_kernel, cudaFuncAttributeMaxDynamicSharedMemorySize, mlp_smem);

    fps_pf_kernel<<<BATCH + BATCH * 8, 512, fps_smem>>>(points, features, w1, b1, cent_out);
    ballq_kernel<<<(BATCH * MCENT * 32) / 256, 256>>>(points, cent_out);
    mlp_kernel<<<BATCH * (MCENT / 4), 128, mlp_smem>>>(
        points, w1, g1, be1, w2, b2, g2, be2, w3, b3, g3, be3, cent_out, out);
}

// round 13
// speedup vs baseline: 2.1229x; 1.3108x over previous
#include <cuda_runtime.h>
#include <cstdint>

#define BATCH 16
#define NPTS  4096
#define CH    64
#define MCENT 1024
#define KNB   32
#define RAD2  0.04f

typedef unsigned long long u64;

// scratch (allocation-free rule: __device__ globals)
__device__ float    g_pf[BATCH * NPTS * 64];   // 16 MB: W1[:,3:]@feat + b1
__device__ unsigned g_prog[BATCH];             // FPS progress (centroids published)
__device__ unsigned g_pfdone;                  // pf blocks completed

// packed f32x2 helpers (sm_100+)
#define PK2(out, lo, hi)  asm("mov.b64 %0, {%1, %2};" : "=l"(out) : "f"(lo), "f"(hi))
#define UPK2(lo, hi, in)  asm("mov.b64 {%0, %1}, %2;" : "=f"(lo), "=f"(hi) : "l"(in))
#define ADD2(o, a, b)     asm("add.rn.f32x2 %0, %1, %2;" : "=l"(o) : "l"(a), "l"(b))
#define MUL2(o, a, b)     asm("mul.rn.f32x2 %0, %1, %2;" : "=l"(o) : "l"(a), "l"(b))
#define FMA2(o, a, b, c)  asm("fma.rn.f32x2 %0, %1, %2, %3;" : "=l"(o) : "l"(a), "l"(b), "l"(c))

#define QBAR(q) asm volatile("bar.sync %0, 128;" :: "r"((q) + 1) : "memory")

__device__ __forceinline__ unsigned ldvol(const unsigned* p) {
    unsigned v; asm volatile("ld.volatile.global.u32 %0, [%1];" : "=r"(v) : "l"(p)); return v;
}

// bufA addressing: stride 68 floats/row + XOR swizzle of float4 index by (r>>3)&3
__device__ __forceinline__ int aidx(int r, int c4) {
    return r * 68 + (((c4 ^ (r >> 3)) & 3) << 2) + ((c4 >> 2) << 4);
}

__global__ void init_kernel() {
    int t = threadIdx.x;
    if (t < BATCH) g_prog[t] = 0u;
    if (t == BATCH) g_pfdone = 0u;
}

// ---------------------------------------------------------------------------
// Packed-f32x2 8x8 register-tile GEMM (R6-proven) from swizzled bufA.
// ---------------------------------------------------------------------------
template <int WS>
__device__ __forceinline__ void gemm8x8p(const float* __restrict__ A,
                                         const float* __restrict__ W,
                                         int r0, int o0, int sw, u64 (&acc)[8][4]) {
#pragma unroll
    for (int i = 0; i < 8; i++)
#pragma unroll
        for (int j = 0; j < 4; j++) acc[i][j] = 0ull;

#pragma unroll 2
    for (int cc = 0; cc < 64; cc += 4) {
        const int c4  = cc >> 2;
        const int pc4 = ((c4 >> 2) << 4) + (((c4 ^ sw) & 3) << 2);
        float4 a[8];
#pragma unroll
        for (int i = 0; i < 8; i++)
            a[i] = *(const float4*)(A + (r0 + i) * 68 + pc4);
#pragma unroll
        for (int j = 0; j < 4; j++) {
            const float* wrow = W + (cc + j) * WS + o0;
            ulonglong2 wA = *(const ulonglong2*)(wrow);
            ulonglong2 wB = *(const ulonglong2*)(wrow + 4);
#pragma unroll
            for (int i = 0; i < 8; i++) {
                float av = (j == 0) ? a[i].x : (j == 1) ? a[i].y : (j == 2) ? a[i].z : a[i].w;
                u64 ap; PK2(ap, av, av);
                FMA2(acc[i][0], ap, wA.x, acc[i][0]);
                FMA2(acc[i][1], ap, wA.y, acc[i][1]);
                FMA2(acc[i][2], ap, wB.x, acc[i][2]);
                FMA2(acc[i][3], ap, wB.y, acc[i][3]);
            }
        }
    }
}

// smem layout constants (floats) for the mlp role
#define SMW_W2   0            // 4096
#define SMW_W3   4096         // 8192
#define SMW_W1P  12288        // 192
#define SMW_S1   12480
#define SMW_BE1  12544
#define SMW_B2   12608
#define SMW_S2   12672
#define SMW_BE2  12736
#define SMW_B3   12800        // 128
#define SMW_S3   12928
#define SMW_BE3  13056
#define SMW_END  13184
#define QSZ      9744         // per-quarter: bufA 8704 + loc 384 + centv 16 + outb 512 + ni 128
#define MEGA_SMEM ((SMW_END + 4 * QSZ) * 4)   // 208,640 B -> 1 block/SM

// ---------------------------------------------------------------------------
// MEGA kernel: bids [0,16) FPS, [16,144) pf, [144,1168) mlp (16 centroids
// per block = 4 quarters x 4 centroids; each quarter = the proven R6 mlp).
// ---------------------------------------------------------------------------
__global__ void __launch_bounds__(512) mega_kernel(
    const float* __restrict__ pts, const float* __restrict__ feats,
    const float* __restrict__ w1, const float* __restrict__ b1,
    const float* __restrict__ g1, const float* __restrict__ be1,
    const float* __restrict__ w2, const float* __restrict__ b2,
    const float* __restrict__ g2, const float* __restrict__ be2,
    const float* __restrict__ w3, const float* __restrict__ b3,
    const float* __restrict__ g3, const float* __restrict__ be3,
    float* __restrict__ cent_out, float* __restrict__ out) {
    extern __shared__ float sm[];
    const int tid = threadIdx.x;

    if (blockIdx.x < BATCH) {
        // =================== FPS (R6-proven, 512 thr, 8 pts/thr) ===========
        float* spx = sm;
        float* spy = sm + NPTS;
        float* spz = sm + 2 * NPTS;
        unsigned* swd = (unsigned*)(sm + 3 * NPTS);   // [2][16]
        unsigned* swn = swd + 32;

        const int b    = blockIdx.x;
        const int lane = tid & 31;
        const int warp = tid >> 5;
        const float* pb = pts + b * 3 * NPTS;

        float xs[8], ys[8], zs[8], dist[8];
#pragma unroll
        for (int i = 0; i < 8; i++) {
            int n = tid + i * 512;
            xs[i] = pb[n]; ys[i] = pb[NPTS + n]; zs[i] = pb[2 * NPTS + n];
            spx[n] = xs[i]; spy[n] = ys[i]; spz[n] = zs[i];
            dist[i] = 1e10f;
        }
        u64 X[4], Y[4], Z[4];
#pragma unroll
        for (int j = 0; j < 4; j++) {
            PK2(X[j], xs[2 * j], xs[2 * j + 1]);
            PK2(Y[j], ys[2 * j], ys[2 * j + 1]);
            PK2(Z[j], zs[2 * j], zs[2 * j + 1]);
        }
        __syncthreads();

        float cx = spx[0], cy = spy[0], cz = spz[0];
        float* centb = cent_out + b * 3 * MCENT;
        if (tid == 0) { centb[0] = cx; centb[MCENT] = cy; centb[2 * MCENT] = cz; }

        int p = 0;
        for (int m = 1; m < MCENT; m++) {
            float ncx = -cx, ncy = -cy, ncz = -cz;
            u64 ncx2, ncy2, ncz2;
            PK2(ncx2, ncx, ncx); PK2(ncy2, ncy, ncy); PK2(ncz2, ncz, ncz);
#pragma unroll
            for (int j = 0; j < 4; j++) {
                u64 dx, dy, dz, t;
                ADD2(dx, X[j], ncx2);
                MUL2(t, dx, dx);
                ADD2(dy, Y[j], ncy2);
                FMA2(t, dy, dy, t);
                ADD2(dz, Z[j], ncz2);
                FMA2(t, dz, dz, t);
                float lo, hi; UPK2(lo, hi, t);
                dist[2 * j]     = fminf(dist[2 * j], lo);
                dist[2 * j + 1] = fminf(dist[2 * j + 1], hi);
            }
            float bd = dist[0]; int bi = 0;
#pragma unroll
            for (int i = 1; i < 8; i++) if (dist[i] > bd) { bd = dist[i]; bi = i; }
            unsigned bn = (unsigned)(tid + bi * 512);
            unsigned du = __float_as_uint(bd);
            unsigned wm = __reduce_max_sync(0xffffffffu, du);
            unsigned cd = (du == wm) ? bn : 0xffffffffu;
            unsigned wi = __reduce_min_sync(0xffffffffu, cd);
            if (lane == 0) { swd[p * 16 + warp] = wm; swn[p * 16 + warp] = wi; }
            __syncthreads();
            unsigned kd = (lane < 16) ? swd[p * 16 + lane] : 0u;
            unsigned kn = (lane < 16) ? swn[p * 16 + lane] : 0xffffffffu;
            unsigned gm = __reduce_max_sync(0xffffffffu, kd);
            unsigned c2 = (kd == gm) ? kn : 0xffffffffu;
            unsigned n  = __reduce_min_sync(0xffffffffu, c2);
            cx = spx[n]; cy = spy[n]; cz = spz[n];
            if (tid == 0) {
                centb[m] = cx; centb[MCENT + m] = cy; centb[2 * MCENT + m] = cz;
                if ((m & 3) == 3) {                 // publish every 4 centroids
                    __threadfence();
                    atomicExch(&g_prog[b], (unsigned)(m + 1));
                }
            }
            p ^= 1;
        }
    } else if (blockIdx.x < BATCH + 128) {
        // =================== pf role (R6-proven, 512 thr) ==================
        float* w1s = sm;            // [c][o] 64*64
        float* b1s = sm + 4096;
        for (int i = tid; i < 64 * 64; i += 512) {
            int c = i >> 6, o = i & 63;
            w1s[i] = w1[o * 67 + 3 + c];
        }
        if (tid < 64) b1s[tid] = b1[tid];
        __syncthreads();

        int bi = blockIdx.x - BATCH;          // 0..127
        int b  = bi >> 3;
        int n  = (bi & 7) * 512 + tid;
        const float* fb = feats + b * CH * NPTS + n;

        float acc[64];
#pragma unroll
        for (int o = 0; o < 64; o++) acc[o] = b1s[o];
#pragma unroll 4
        for (int c = 0; c < 64; c++) {
            float f = fb[c * NPTS];
#pragma unroll
            for (int o = 0; o < 64; o += 4) {
                float4 w = *(const float4*)&w1s[(c << 6) + o];
                acc[o]     = fmaf(w.x, f, acc[o]);
                acc[o + 1] = fmaf(w.y, f, acc[o + 1]);
                acc[o + 2] = fmaf(w.z, f, acc[o + 2]);
                acc[o + 3] = fmaf(w.w, f, acc[o + 3]);
            }
        }
        float* dst = g_pf + (b * NPTS + n) * 64;
#pragma unroll
        for (int o = 0; o < 64; o += 4)
            *(float4*)(dst + o) = make_float4(acc[o], acc[o + 1], acc[o + 2], acc[o + 3]);
        __threadfence();
        __syncthreads();
        if (tid == 0) atomicAdd(&g_pfdone, 1u);
    } else {
        // =================== mlp role: 4 quarters x 4 centroids ============
        float* w2s  = sm + SMW_W2;
        float* w3s  = sm + SMW_W3;
        float* w1ps = sm + SMW_W1P;
        float* s1   = sm + SMW_S1;
        float* be1s = sm + SMW_BE1;
        float* b2s  = sm + SMW_B2;
        float* s2   = sm + SMW_S2;
        float* be2s = sm + SMW_BE2;
        float* b3s  = sm + SMW_B3;
        float* s3   = sm + SMW_S3;
        float* be3s = sm + SMW_BE3;

        const int i     = blockIdx.x - BATCH - 128;    // 0..1023
        const int b     = i & 15;
        const int mbase = (i >> 4) << 4;               // 16 centroids per block
        const int q     = tid >> 7;                    // quarter 0..3
        const int qtid  = tid & 127;
        const int m0    = mbase + q * 4;
        const float rs  = rsqrtf(1.0f + 1e-5f);

        float* bufA  = sm + SMW_END + q * QSZ;         // 8704 (swizzled)
        float* loc   = bufA + 8704;                    // [3][128]
        float* centv = loc + 384;                      // [4][3] (+pad)
        int*   outb  = (int*)(centv + 16);             // [4][128]
        int*   ni_q  = outb + 512;                     // [4][32]

        // cooperative shared-weight load (512 threads, independent of FPS)
        for (int k = tid; k < 4096; k += 512) { int c = k >> 6, o = k & 63;  w2s[k] = w2[o * 64 + c]; }
        for (int k = tid; k < 8192; k += 512) { int c = k >> 7, o = k & 127; w3s[k] = w3[o * 64 + c]; }
        if (tid < 192) { int d = tid >> 6, o = tid & 63; w1ps[tid] = w1[o * 67 + d]; }
        if (tid < 64) {
            s1[tid] = g1[tid] * rs; be1s[tid] = be1[tid];
            b2s[tid] = b2[tid]; s2[tid] = g2[tid] * rs; be2s[tid] = be2[tid];
        }
        if (tid < 128) { b3s[tid] = b3[tid]; s3[tid] = g3[tid] * rs; be3s[tid] = be3[tid]; }
        __syncthreads();

        // per-quarter from here on (named barrier q+1, 128 threads)
        for (int k = qtid; k < 512; k += 128) outb[k] = 0;
        if (qtid == 0) {
            while (ldvol(&g_pfdone) < 128u) __nanosleep(128);
            while (ldvol(&g_prog[b]) < (unsigned)(m0 + 4)) __nanosleep(128);
            __threadfence();
        }
        QBAR(q);
        if (qtid < 12)   // centroid coords via L2 (L1 may hold a stale line)
            centv[qtid] = __ldcg(cent_out + b * 3 * MCENT + (qtid % 3) * MCENT + m0 + qtid / 3);
        QBAR(q);

        // ball query: warp wq -> centroid wq, full ordered scan (R6 algorithm)
        {
            const int wq = qtid >> 5, lane = qtid & 31;
            const float* pb = pts + b * 3 * NPTS;
            float cx = centv[wq * 3], cy = centv[wq * 3 + 1], cz = centv[wq * 3 + 2];
            float c2 = cx * cx + cy * cy + cz * cz;
            int* nis = ni_q + wq * 32;
            int cnt = 0, first = -1;
            for (int base = 0; base < NPTS; base += 32) {
                int n = base + lane;
                float x = pb[n], y = pb[NPTS + n], z = pb[2 * NPTS + n];
                float p2  = x * x + y * y + z * z;
                float dot = cx * x + cy * y + cz * z;
                float d2  = c2 + p2 - 2.f * dot;
                bool hit = (d2 <= RAD2);
                unsigned mask = __ballot_sync(0xffffffffu, hit);
                if (mask) {
                    if (first < 0) first = base + __ffs(mask) - 1;
                    if (hit) {
                        int rank = cnt + __popc(mask & ((1u << lane) - 1u));
                        if (rank < KNB) nis[rank] = n;
                    }
                    cnt += __popc(mask);
                    if (cnt >= KNB) break;
                }
            }
            if (cnt < KNB) {
                int f = (first < 0) ? (NPTS - 1) : first;
                for (int s = cnt + lane; s < KNB; s += 32) nis[s] = f;
            }
        }
        QBAR(q);

        // gather: warp w handles group w (32 rows); writes swizzled float2s
        {
            const int w = qtid >> 5, lane = qtid & 31;
            const float* pb = pts + b * 3 * NPTS;
            float cx = centv[w * 3], cy = centv[w * 3 + 1], cz = centv[w * 3 + 2];
            int nk = ni_q[w * 32 + lane];
#pragma unroll 4
            for (int k = 0; k < KNB; k++) {
                int n = __shfl_sync(0xffffffffu, nk, k);
                int r = w * 32 + k;
                if (lane == 0) {
                    loc[r]       = pb[n] - cx;
                    loc[128 + r] = pb[NPTS + n] - cy;
                    loc[256 + r] = pb[2 * NPTS + n] - cz;
                }
                float2 v = *(const float2*)(g_pf + (b * NPTS + n) * 64 + lane * 2);
                *(float2*)(bufA + aidx(r, lane >> 1) + ((lane & 1) << 1)) = v;
            }
        }
        QBAR(q);

        // layer 1: in place in bufA
        {
            const int r = qtid;
            float lx = loc[r], ly = loc[128 + r], lz = loc[256 + r];
#pragma unroll
            for (int o = 0; o < 64; o += 4) {
                float* ap = bufA + aidx(r, o >> 2);
                float4 p  = *(float4*)ap;
                float4 wx = *(const float4*)(w1ps + o);
                float4 wy = *(const float4*)(w1ps + 64 + o);
                float4 wz = *(const float4*)(w1ps + 128 + o);
                float4 sc = *(const float4*)(s1 + o);
                float4 eb = *(const float4*)(be1s + o);
                p.x = fmaf(wz.x, lz, fmaf(wy.x, ly, fmaf(wx.x, lx, p.x)));
                p.y = fmaf(wz.y, lz, fmaf(wy.y, ly, fmaf(wx.y, lx, p.y)));
                p.z = fmaf(wz.z, lz, fmaf(wy.z, ly, fmaf(wx.z, lx, p.z)));
                p.w = fmaf(wz.w, lz, fmaf(wy.w, ly, fmaf(wx.w, lx, p.w)));
                p.x = fmaxf(fmaf(p.x, sc.x, eb.x), 0.f);
                p.y = fmaxf(fmaf(p.y, sc.y, eb.y), 0.f);
                p.z = fmaxf(fmaf(p.z, sc.z, eb.z), 0.f);
                p.w = fmaxf(fmaf(p.w, sc.w, eb.w), 0.f);
                *(float4*)ap = p;
            }
        }
        QBAR(q);

        const int rt = qtid >> 3, ct = qtid & 7;
        const int r0 = rt * 8, o0 = ct * 8;
        const int sw = rt & 3;

        // layer 2 IN PLACE
        {
            u64 acc[8][4];
            gemm8x8p<64>(bufA, w2s, r0, o0, sw, acc);
            float ac[8][8];
#pragma unroll
            for (int ii = 0; ii < 8; ii++)
#pragma unroll
                for (int j = 0; j < 4; j++) UPK2(ac[ii][2 * j], ac[ii][2 * j + 1], acc[ii][j]);
            float4 bb0 = *(const float4*)(b2s + o0),  bb1 = *(const float4*)(b2s + o0 + 4);
            float4 ss0 = *(const float4*)(s2 + o0),   ss1 = *(const float4*)(s2 + o0 + 4);
            float4 ee0 = *(const float4*)(be2s + o0), ee1 = *(const float4*)(be2s + o0 + 4);
#pragma unroll
            for (int ii = 0; ii < 8; ii++) {
                ac[ii][0] = fmaxf(fmaf(ac[ii][0] + bb0.x, ss0.x, ee0.x), 0.f);
                ac[ii][1] = fmaxf(fmaf(ac[ii][1] + bb0.y, ss0.y, ee0.y), 0.f);
                ac[ii][2] = fmaxf(fmaf(ac[ii][2] + bb0.z, ss0.z, ee0.z), 0.f);
                ac[ii][3] = fmaxf(fmaf(ac[ii][3] + bb0.w, ss0.w, ee0.w), 0.f);
                ac[ii][4] = fmaxf(fmaf(ac[ii][4] + bb1.x, ss1.x, ee1.x), 0.f);
                ac[ii][5] = fmaxf(fmaf(ac[ii][5] + bb1.y, ss1.y, ee1.y), 0.f);
                ac[ii][6] = fmaxf(fmaf(ac[ii][6] + bb1.z, ss1.z, ee1.z), 0.f);
                ac[ii][7] = fmaxf(fmaf(ac[ii][7] + bb1.w, ss1.w, ee1.w), 0.f);
            }
            QBAR(q);   // all gemm reads of bufA complete
            const int c4a = o0 >> 2;
#pragma unroll
            for (int ii = 0; ii < 8; ii++) {
                *(float4*)(bufA + aidx(r0 + ii, c4a)) =
                    make_float4(ac[ii][0], ac[ii][1], ac[ii][2], ac[ii][3]);
                *(float4*)(bufA + aidx(r0 + ii, c4a + 1)) =
                    make_float4(ac[ii][4], ac[ii][5], ac[ii][6], ac[ii][7]);
            }
        }
        QBAR(q);

        // layer 3 (two col passes over full w3s) + fused maxpool
        const int gg = r0 >> 5;
#pragma unroll 1
        for (int pp = 0; pp < 2; pp++) {
            const int q0 = o0 + pp * 64;
            u64 acc[8][4];
            gemm8x8p<128>(bufA, w3s, r0, q0, sw, acc);
            float ac[8][8];
#pragma unroll
            for (int ii = 0; ii < 8; ii++)
#pragma unroll
                for (int j = 0; j < 4; j++) UPK2(ac[ii][2 * j], ac[ii][2 * j + 1], acc[ii][j]);
            float4 bb0 = *(const float4*)(b3s + q0),  bb1 = *(const float4*)(b3s + q0 + 4);
            float4 ss0 = *(const float4*)(s3 + q0),   ss1 = *(const float4*)(s3 + q0 + 4);
            float4 ee0 = *(const float4*)(be3s + q0), ee1 = *(const float4*)(be3s + q0 + 4);
            float cm[8];
#pragma unroll
            for (int j = 0; j < 8; j++) cm[j] = 0.f;
#pragma unroll
            for (int ii = 0; ii < 8; ii++) {
                cm[0] = fmaxf(cm[0], fmaxf(fmaf(ac[ii][0] + bb0.x, ss0.x, ee0.x), 0.f));
                cm[1] = fmaxf(cm[1], fmaxf(fmaf(ac[ii][1] + bb0.y, ss0.y, ee0.y), 0.f));
                cm[2] = fmaxf(cm[2], fmaxf(fmaf(ac[ii][2] + bb0.z, ss0.z, ee0.z), 0.f));
                cm[3] = fmaxf(cm[3], fmaxf(fmaf(ac[ii][3] + bb0.w, ss0.w, ee0.w), 0.f));
                cm[4] = fmaxf(cm[4], fmaxf(fmaf(ac[ii][4] + bb1.x, ss1.x, ee1.x), 0.f));
                cm[5] = fmaxf(cm[5], fmaxf(fmaf(ac[ii][5] + bb1.y, ss1.y, ee1.y), 0.f));
                cm[6] = fmaxf(cm[6], fmaxf(fmaf(ac[ii][6] + bb1.z, ss1.z, ee1.z), 0.f));
                cm[7] = fmaxf(cm[7], fmaxf(fmaf(ac[ii][7] + bb1.w, ss1.w, ee1.w), 0.f));
            }
#pragma unroll
            for (int j = 0; j < 8; j++)
                atomicMax(&outb[gg * 128 + q0 + j], __float_as_int(cm[j]));
        }
        QBAR(q);

        // write out[b][o][m0..m0+3]
        {
            int o = qtid;
            float4 v;
            v.x = __int_as_float(outb[0 * 128 + o]);
            v.y = __int_as_float(outb[1 * 128 + o]);
            v.z = __int_as_float(outb[2 * 128 + o]);
            v.w = __int_as_float(outb[3 * 128 + o]);
            *(float4*)(out + (b * 128 + o) * MCENT + m0) = v;
        }
    }
}

// ---------------------------------------------------------------------------
extern "C" void kernel_launch(void* const* d_in, const int* in_sizes, int n_in,
                              void* d_out, int out_size) {
    const float* points   = (const float*)d_in[0];
    const float* features = (const float*)d_in[1];
    const float* w1  = (const float*)d_in[2];
    const float* b1  = (const float*)d_in[3];
    const float* g1  = (const float*)d_in[4];
    const float* be1 = (const float*)d_in[5];
    const float* w2  = (const float*)d_in[6];
    const float* b2  = (const float*)d_in[7];
    const float* g2  = (const float*)d_in[8];
    const float* be2 = (const float*)d_in[9];
    const float* w3  = (const float*)d_in[10];
    const float* b3  = (const float*)d_in[11];
    const float* g3  = (const float*)d_in[12];
    const float* be3 = (const float*)d_in[13];

    float* cent_out = (float*)d_out;                       // [B][3][M]
    float* out      = cent_out + BATCH * 3 * MCENT;        // [B][128][M]

    cudaFuncSetAttribute(mega_kernel, cudaFuncAttributeMaxDynamicSharedMemorySize, MEGA_SMEM);

    init_kernel<<<1, 32>>>();
    mega_kernel<<<BATCH + 128 + BATCH * (MCENT / 16), 512, MEGA_SMEM>>>(
        points, features, w1, b1, g1, be1, w2, b2, g2, be2, w3, b3, g3, be3,
        cent_out, out);
}

// round 14
// speedup vs baseline: 2.7604x; 1.3003x over previous
#include <cuda_runtime.h>
#include <cstdint>

#define BATCH 16
#define NPTS  4096
#define CH    64
#define MCENT 1024
#define KNB   32
#define RAD2  0.04f

typedef unsigned long long u64;

// scratch (allocation-free rule: __device__ globals)
__device__ float    g_pf[BATCH * NPTS * 64];   // 16 MB: W1[:,3:]@feat + b1
__device__ unsigned g_prog[BATCH];             // FPS progress (centroids published)
__device__ unsigned g_pfdone;                  // pf blocks completed
__device__ unsigned g_ticket;                  // consumer work queue

// packed f32x2 helpers (sm_100+)
#define PK2(out, lo, hi)  asm("mov.b64 %0, {%1, %2};" : "=l"(out) : "f"(lo), "f"(hi))
#define UPK2(lo, hi, in)  asm("mov.b64 {%0, %1}, %2;" : "=f"(lo), "=f"(hi) : "l"(in))
#define ADD2(o, a, b)     asm("add.rn.f32x2 %0, %1, %2;" : "=l"(o) : "l"(a), "l"(b))
#define MUL2(o, a, b)     asm("mul.rn.f32x2 %0, %1, %2;" : "=l"(o) : "l"(a), "l"(b))
#define FMA2(o, a, b, c)  asm("fma.rn.f32x2 %0, %1, %2, %3;" : "=l"(o) : "l"(a), "l"(b), "l"(c))

#define QBAR(q) asm volatile("bar.sync %0, 128;" :: "r"((q) + 1) : "memory")

__device__ __forceinline__ unsigned ldacq(const unsigned* p) {
    unsigned v; asm volatile("ld.acquire.gpu.global.u32 %0, [%1];" : "=r"(v) : "l"(p)); return v;
}

// bufA addressing: stride 68 floats/row + XOR swizzle of float4 index by (r>>3)&3
__device__ __forceinline__ int aidx(int r, int c4) {
    return r * 68 + (((c4 ^ (r >> 3)) & 3) << 2) + ((c4 >> 2) << 4);
}

__global__ void init_kernel() {
    int t = threadIdx.x;
    if (t < BATCH) g_prog[t] = 0u;
    if (t == BATCH) g_pfdone = 0u;
    if (t == BATCH + 1) g_ticket = 0u;
}

// ---------------------------------------------------------------------------
// Packed-f32x2 8x8 register-tile GEMM (R6-proven) from swizzled bufA.
// ---------------------------------------------------------------------------
template <int WS>
__device__ __forceinline__ void gemm8x8p(const float* __restrict__ A,
                                         const float* __restrict__ W,
                                         int r0, int o0, int sw, u64 (&acc)[8][4]) {
#pragma unroll
    for (int i = 0; i < 8; i++)
#pragma unroll
        for (int j = 0; j < 4; j++) acc[i][j] = 0ull;

#pragma unroll 2
    for (int cc = 0; cc < 64; cc += 4) {
        const int c4  = cc >> 2;
        const int pc4 = ((c4 >> 2) << 4) + (((c4 ^ sw) & 3) << 2);
        float4 a[8];
#pragma unroll
        for (int i = 0; i < 8; i++)
            a[i] = *(const float4*)(A + (r0 + i) * 68 + pc4);
#pragma unroll
        for (int j = 0; j < 4; j++) {
            const float* wrow = W + (cc + j) * WS + o0;
            ulonglong2 wA = *(const ulonglong2*)(wrow);
            ulonglong2 wB = *(const ulonglong2*)(wrow + 4);
#pragma unroll
            for (int i = 0; i < 8; i++) {
                float av = (j == 0) ? a[i].x : (j == 1) ? a[i].y : (j == 2) ? a[i].z : a[i].w;
                u64 ap; PK2(ap, av, av);
                FMA2(acc[i][0], ap, wA.x, acc[i][0]);
                FMA2(acc[i][1], ap, wA.y, acc[i][1]);
                FMA2(acc[i][2], ap, wB.x, acc[i][2]);
                FMA2(acc[i][3], ap, wB.y, acc[i][3]);
            }
        }
    }
}

// smem layout constants (floats) for the worker role
#define SMW_W2   0            // 4096
#define SMW_W3   4096         // 8192
#define SMW_W1P  12288        // 192
#define SMW_S1   12480
#define SMW_BE1  12544
#define SMW_B2   12608
#define SMW_S2   12672
#define SMW_BE2  12736
#define SMW_B3   12800        // 128
#define SMW_S3   12928
#define SMW_BE3  13056
#define SMW_END  13184
#define QSZ      9760         // bufA 8704 + loc 384 + centv 16 + outb 512 + ni 128 + tick 16
#define MEGA_SMEM ((SMW_END + 4 * QSZ) * 4)   // 208,896 B -> 1 block/SM
#define NITEMS   (BATCH * MCENT / 4)          // 4096 work items (4 centroids each)

// ---------------------------------------------------------------------------
// MEGA kernel: bids [0,16) FPS, [16,144) pf, [144,308) persistent workers
// (each worker block = 4 independent quarters pulling 4-centroid tickets).
// ---------------------------------------------------------------------------
__global__ void __launch_bounds__(512) mega_kernel(
    const float* __restrict__ pts, const float* __restrict__ feats,
    const float* __restrict__ w1, const float* __restrict__ b1,
    const float* __restrict__ g1, const float* __restrict__ be1,
    const float* __restrict__ w2, const float* __restrict__ b2,
    const float* __restrict__ g2, const float* __restrict__ be2,
    const float* __restrict__ w3, const float* __restrict__ b3,
    const float* __restrict__ g3, const float* __restrict__ be3,
    float* __restrict__ cent_out, float* __restrict__ out) {
    extern __shared__ float sm[];
    const int tid = threadIdx.x;

    if (blockIdx.x < BATCH) {
        // =================== FPS (R6-proven, 512 thr, 8 pts/thr) ===========
        float* spx = sm;
        float* spy = sm + NPTS;
        float* spz = sm + 2 * NPTS;
        unsigned* swd = (unsigned*)(sm + 3 * NPTS);   // [2][16]
        unsigned* swn = swd + 32;

        const int b    = blockIdx.x;
        const int lane = tid & 31;
        const int warp = tid >> 5;
        const float* pb = pts + b * 3 * NPTS;

        float xs[8], ys[8], zs[8], dist[8];
#pragma unroll
        for (int i = 0; i < 8; i++) {
            int n = tid + i * 512;
            xs[i] = pb[n]; ys[i] = pb[NPTS + n]; zs[i] = pb[2 * NPTS + n];
            spx[n] = xs[i]; spy[n] = ys[i]; spz[n] = zs[i];
            dist[i] = 1e10f;
        }
        u64 X[4], Y[4], Z[4];
#pragma unroll
        for (int j = 0; j < 4; j++) {
            PK2(X[j], xs[2 * j], xs[2 * j + 1]);
            PK2(Y[j], ys[2 * j], ys[2 * j + 1]);
            PK2(Z[j], zs[2 * j], zs[2 * j + 1]);
        }
        __syncthreads();

        float cx = spx[0], cy = spy[0], cz = spz[0];
        float* centb = cent_out + b * 3 * MCENT;
        if (tid == 0) { centb[0] = cx; centb[MCENT] = cy; centb[2 * MCENT] = cz; }

        int p = 0;
        for (int m = 1; m < MCENT; m++) {
            float ncx = -cx, ncy = -cy, ncz = -cz;
            u64 ncx2, ncy2, ncz2;
            PK2(ncx2, ncx, ncx); PK2(ncy2, ncy, ncy); PK2(ncz2, ncz, ncz);
#pragma unroll
            for (int j = 0; j < 4; j++) {
                u64 dx, dy, dz, t;
                ADD2(dx, X[j], ncx2);
                MUL2(t, dx, dx);
                ADD2(dy, Y[j], ncy2);
                FMA2(t, dy, dy, t);
                ADD2(dz, Z[j], ncz2);
                FMA2(t, dz, dz, t);
                float lo, hi; UPK2(lo, hi, t);
                dist[2 * j]     = fminf(dist[2 * j], lo);
                dist[2 * j + 1] = fminf(dist[2 * j + 1], hi);
            }
            float bd = dist[0]; int bi = 0;
#pragma unroll
            for (int i = 1; i < 8; i++) if (dist[i] > bd) { bd = dist[i]; bi = i; }
            unsigned bn = (unsigned)(tid + bi * 512);
            unsigned du = __float_as_uint(bd);
            unsigned wm = __reduce_max_sync(0xffffffffu, du);
            unsigned cd = (du == wm) ? bn : 0xffffffffu;
            unsigned wi = __reduce_min_sync(0xffffffffu, cd);
            if (lane == 0) { swd[p * 16 + warp] = wm; swn[p * 16 + warp] = wi; }
            __syncthreads();
            unsigned kd = (lane < 16) ? swd[p * 16 + lane] : 0u;
            unsigned kn = (lane < 16) ? swn[p * 16 + lane] : 0xffffffffu;
            unsigned gm = __reduce_max_sync(0xffffffffu, kd);
            unsigned c2 = (kd == gm) ? kn : 0xffffffffu;
            unsigned n  = __reduce_min_sync(0xffffffffu, c2);
            cx = spx[n]; cy = spy[n]; cz = spz[n];
            if (tid == 0) {
                centb[m] = cx; centb[MCENT + m] = cy; centb[2 * MCENT + m] = cz;
                if ((m & 3) == 3)   // publish every 4 centroids (release store)
                    asm volatile("st.release.gpu.global.u32 [%0], %1;"
                                 :: "l"(g_prog + b), "r"((unsigned)(m + 1)) : "memory");
            }
            p ^= 1;
        }
    } else if (blockIdx.x < BATCH + 128) {
        // =================== pf role (R6-proven, 512 thr) ==================
        float* w1s = sm;            // [c][o] 64*64
        float* b1s = sm + 4096;
        for (int i = tid; i < 64 * 64; i += 512) {
            int c = i >> 6, o = i & 63;
            w1s[i] = w1[o * 67 + 3 + c];
        }
        if (tid < 64) b1s[tid] = b1[tid];
        __syncthreads();

        int bi = blockIdx.x - BATCH;          // 0..127
        int b  = bi >> 3;
        int n  = (bi & 7) * 512 + tid;
        const float* fb = feats + b * CH * NPTS + n;

        float acc[64];
#pragma unroll
        for (int o = 0; o < 64; o++) acc[o] = b1s[o];
#pragma unroll 4
        for (int c = 0; c < 64; c++) {
            float f = fb[c * NPTS];
#pragma unroll
            for (int o = 0; o < 64; o += 4) {
                float4 w = *(const float4*)&w1s[(c << 6) + o];
                acc[o]     = fmaf(w.x, f, acc[o]);
                acc[o + 1] = fmaf(w.y, f, acc[o + 1]);
                acc[o + 2] = fmaf(w.z, f, acc[o + 2]);
                acc[o + 3] = fmaf(w.w, f, acc[o + 3]);
            }
        }
        float* dst = g_pf + (b * NPTS + n) * 64;
#pragma unroll
        for (int o = 0; o < 64; o += 4)
            *(float4*)(dst + o) = make_float4(acc[o], acc[o + 1], acc[o + 2], acc[o + 3]);
        __threadfence();
        __syncthreads();
        if (tid == 0) atomicAdd(&g_pfdone, 1u);
    } else {
        // =================== persistent worker: 4 quarters =================
        float* w2s  = sm + SMW_W2;
        float* w3s  = sm + SMW_W3;
        float* w1ps = sm + SMW_W1P;
        float* s1   = sm + SMW_S1;
        float* be1s = sm + SMW_BE1;
        float* b2s  = sm + SMW_B2;
        float* s2   = sm + SMW_S2;
        float* be2s = sm + SMW_BE2;
        float* b3s  = sm + SMW_B3;
        float* s3   = sm + SMW_S3;
        float* be3s = sm + SMW_BE3;

        const int q    = tid >> 7;                    // quarter 0..3
        const int qtid = tid & 127;
        const float rs = rsqrtf(1.0f + 1e-5f);

        float*    bufA  = sm + SMW_END + q * QSZ;     // 8704 (swizzled)
        float*    loc   = bufA + 8704;                // [3][128]
        float*    centv = loc + 384;                  // [4][3] (+pad)
        int*      outb  = (int*)(centv + 16);         // [4][128]
        int*      ni_q  = outb + 512;                 // [4][32]
        unsigned* tick  = (unsigned*)(ni_q + 128);    // quarter ticket slot

        // one-time weight load (block-wide)
        for (int k = tid; k < 4096; k += 512) { int c = k >> 6, o = k & 63;  w2s[k] = w2[o * 64 + c]; }
        for (int k = tid; k < 8192; k += 512) { int c = k >> 7, o = k & 127; w3s[k] = w3[o * 64 + c]; }
        if (tid < 192) { int d = tid >> 6, o = tid & 63; w1ps[tid] = w1[o * 67 + d]; }
        if (tid < 64) {
            s1[tid] = g1[tid] * rs; be1s[tid] = be1[tid];
            b2s[tid] = b2[tid]; s2[tid] = g2[tid] * rs; be2s[tid] = be2[tid];
        }
        if (tid < 128) { b3s[tid] = b3[tid]; s3[tid] = g3[tid] * rs; be3s[tid] = be3[tid]; }
        __syncthreads();

        // one-time pf gate (per quarter)
        if (qtid == 0) { while (ldacq(&g_pfdone) < 128u) __nanosleep(256); }
        QBAR(q);

        const int rt = qtid >> 3, ct = qtid & 7;
        const int r0 = rt * 8, o0 = ct * 8;
        const int sw = rt & 3;
        const int lane = qtid & 31, wq = qtid >> 5;

        for (;;) {
            if (qtid == 0) tick[0] = atomicAdd(&g_ticket, 1u);
            QBAR(q);
            const unsigned t = tick[0];
            if (t >= NITEMS) break;
            const int b  = (int)(t & 15u);
            const int m0 = (int)((t >> 4) << 2);
            const float* pb = pts + b * 3 * NPTS;

            for (int k = qtid; k < 512; k += 128) outb[k] = 0;
            if (qtid == 0) {
                while (ldacq(&g_prog[b]) < (unsigned)(m0 + 4)) __nanosleep(128);
            }
            QBAR(q);
            if (qtid < 12)   // centroid coords via L2 (L1 may hold a stale line)
                centv[qtid] = __ldcg(cent_out + b * 3 * MCENT + (qtid % 3) * MCENT + m0 + qtid / 3);
            QBAR(q);

            // ball query: warp wq -> centroid wq, 64 pts/iter (dual ballot)
            {
                float cx = centv[wq * 3], cy = centv[wq * 3 + 1], cz = centv[wq * 3 + 2];
                float c2 = cx * cx + cy * cy + cz * cz;
                int* nis = ni_q + wq * 32;
                int cnt = 0, first = -1;
                const unsigned below = (1u << lane) - 1u;
                for (int base = 0; base < NPTS; base += 64) {
                    int n0 = base + 2 * lane;
                    float2 x2 = *(const float2*)(pb + n0);
                    float2 y2 = *(const float2*)(pb + NPTS + n0);
                    float2 z2 = *(const float2*)(pb + 2 * NPTS + n0);
                    float d2a = c2 + (x2.x * x2.x + y2.x * y2.x + z2.x * z2.x)
                              - 2.f * (cx * x2.x + cy * y2.x + cz * z2.x);
                    float d2b = c2 + (x2.y * x2.y + y2.y * y2.y + z2.y * z2.y)
                              - 2.f * (cx * x2.y + cy * y2.y + cz * z2.y);
                    bool h0 = (d2a <= RAD2), h1 = (d2b <= RAD2);
                    unsigned mE = __ballot_sync(0xffffffffu, h0);
                    unsigned mO = __ballot_sync(0xffffffffu, h1);
                    if (mE | mO) {
                        if (first < 0) {
                            int fe = mE ? 2 * (__ffs(mE) - 1)     : 0x7fff;
                            int fo = mO ? 2 * (__ffs(mO) - 1) + 1 : 0x7fff;
                            first = base + min(fe, fo);
                        }
                        if (h0) {
                            int r = cnt + __popc(mE & below) + __popc(mO & below);
                            if (r < KNB) nis[r] = n0;
                        }
                        if (h1) {
                            int r = cnt + __popc(mE & (below | (1u << lane))) + __popc(mO & below);
                            if (r < KNB) nis[r] = n0 + 1;
                        }
                        cnt += __popc(mE) + __popc(mO);
                        if (cnt >= KNB) break;
                    }
                }
                if (cnt < KNB) {
                    int f = (first < 0) ? (NPTS - 1) : first;
                    for (int s = cnt + lane; s < KNB; s += 32) nis[s] = f;
                }
            }
            QBAR(q);

            // gather: warp wq -> group wq rows
            {
                float cx = centv[wq * 3], cy = centv[wq * 3 + 1], cz = centv[wq * 3 + 2];
                int nk = ni_q[wq * 32 + lane];
#pragma unroll 4
                for (int k = 0; k < KNB; k++) {
                    int n = __shfl_sync(0xffffffffu, nk, k);
                    int r = wq * 32 + k;
                    if (lane == 0) {
                        loc[r]       = pb[n] - cx;
                        loc[128 + r] = pb[NPTS + n] - cy;
                        loc[256 + r] = pb[2 * NPTS + n] - cz;
                    }
                    float2 v = *(const float2*)(g_pf + (b * NPTS + n) * 64 + lane * 2);
                    *(float2*)(bufA + aidx(r, lane >> 1) + ((lane & 1) << 1)) = v;
                }
            }
            QBAR(q);

            // layer 1: in place in bufA
            {
                const int r = qtid;
                float lx = loc[r], ly = loc[128 + r], lz = loc[256 + r];
#pragma unroll
                for (int o = 0; o < 64; o += 4) {
                    float* ap = bufA + aidx(r, o >> 2);
                    float4 p  = *(float4*)ap;
                    float4 wx = *(const float4*)(w1ps + o);
                    float4 wy = *(const float4*)(w1ps + 64 + o);
                    float4 wz = *(const float4*)(w1ps + 128 + o);
                    float4 sc = *(const float4*)(s1 + o);
                    float4 eb = *(const float4*)(be1s + o);
                    p.x = fmaf(wz.x, lz, fmaf(wy.x, ly, fmaf(wx.x, lx, p.x)));
                    p.y = fmaf(wz.y, lz, fmaf(wy.y, ly, fmaf(wx.y, lx, p.y)));
                    p.z = fmaf(wz.z, lz, fmaf(wy.z, ly, fmaf(wx.z, lx, p.z)));
                    p.w = fmaf(wz.w, lz, fmaf(wy.w, ly, fmaf(wx.w, lx, p.w)));
                    p.x = fmaxf(fmaf(p.x, sc.x, eb.x), 0.f);
                    p.y = fmaxf(fmaf(p.y, sc.y, eb.y), 0.f);
                    p.z = fmaxf(fmaf(p.z, sc.z, eb.z), 0.f);
                    p.w = fmaxf(fmaf(p.w, sc.w, eb.w), 0.f);
                    *(float4*)ap = p;
                }
            }
            QBAR(q);

            // layer 2 IN PLACE
            {
                u64 acc[8][4];
                gemm8x8p<64>(bufA, w2s, r0, o0, sw, acc);
                float ac[8][8];
#pragma unroll
                for (int ii = 0; ii < 8; ii++)
#pragma unroll
                    for (int j = 0; j < 4; j++) UPK2(ac[ii][2 * j], ac[ii][2 * j + 1], acc[ii][j]);
                float4 bb0 = *(const float4*)(b2s + o0),  bb1 = *(const float4*)(b2s + o0 + 4);
                float4 ss0 = *(const float4*)(s2 + o0),   ss1 = *(const float4*)(s2 + o0 + 4);
                float4 ee0 = *(const float4*)(be2s + o0), ee1 = *(const float4*)(be2s + o0 + 4);
#pragma unroll
                for (int ii = 0; ii < 8; ii++) {
                    ac[ii][0] = fmaxf(fmaf(ac[ii][0] + bb0.x, ss0.x, ee0.x), 0.f);
                    ac[ii][1] = fmaxf(fmaf(ac[ii][1] + bb0.y, ss0.y, ee0.y), 0.f);
                    ac[ii][2] = fmaxf(fmaf(ac[ii][2] + bb0.z, ss0.z, ee0.z), 0.f);
                    ac[ii][3] = fmaxf(fmaf(ac[ii][3] + bb0.w, ss0.w, ee0.w), 0.f);
                    ac[ii][4] = fmaxf(fmaf(ac[ii][4] + bb1.x, ss1.x, ee1.x), 0.f);
                    ac[ii][5] = fmaxf(fmaf(ac[ii][5] + bb1.y, ss1.y, ee1.y), 0.f);
                    ac[ii][6] = fmaxf(fmaf(ac[ii][6] + bb1.z, ss1.z, ee1.z), 0.f);
                    ac[ii][7] = fmaxf(fmaf(ac[ii][7] + bb1.w, ss1.w, ee1.w), 0.f);
                }
                QBAR(q);   // all gemm reads of bufA complete
                const int c4a = o0 >> 2;
#pragma unroll
                for (int ii = 0; ii < 8; ii++) {
                    *(float4*)(bufA + aidx(r0 + ii, c4a)) =
                        make_float4(ac[ii][0], ac[ii][1], ac[ii][2], ac[ii][3]);
                    *(float4*)(bufA + aidx(r0 + ii, c4a + 1)) =
                        make_float4(ac[ii][4], ac[ii][5], ac[ii][6], ac[ii][7]);
                }
            }
            QBAR(q);

            // layer 3 (two col passes) + fused maxpool
            const int gg = r0 >> 5;
#pragma unroll 1
            for (int pp = 0; pp < 2; pp++) {
                const int q0 = o0 + pp * 64;
                u64 acc[8][4];
                gemm8x8p<128>(bufA, w3s, r0, q0, sw, acc);
                float ac[8][8];
#pragma unroll
                for (int ii = 0; ii < 8; ii++)
#pragma unroll
                    for (int j = 0; j < 4; j++) UPK2(ac[ii][2 * j], ac[ii][2 * j + 1], acc[ii][j]);
                float4 bb0 = *(const float4*)(b3s + q0),  bb1 = *(const float4*)(b3s + q0 + 4);
                float4 ss0 = *(const float4*)(s3 + q0),   ss1 = *(const float4*)(s3 + q0 + 4);
                float4 ee0 = *(const float4*)(be3s + q0), ee1 = *(const float4*)(be3s + q0 + 4);
                float cm[8];
#pragma unroll
                for (int j = 0; j < 8; j++) cm[j] = 0.f;
#pragma unroll
                for (int ii = 0; ii < 8; ii++) {
                    cm[0] = fmaxf(cm[0], fmaxf(fmaf(ac[ii][0] + bb0.x, ss0.x, ee0.x), 0.f));
                    cm[1] = fmaxf(cm[1], fmaxf(fmaf(ac[ii][1] + bb0.y, ss0.y, ee0.y), 0.f));
                    cm[2] = fmaxf(cm[2], fmaxf(fmaf(ac[ii][2] + bb0.z, ss0.z, ee0.z), 0.f));
                    cm[3] = fmaxf(cm[3], fmaxf(fmaf(ac[ii][3] + bb0.w, ss0.w, ee0.w), 0.f));
                    cm[4] = fmaxf(cm[4], fmaxf(fmaf(ac[ii][4] + bb1.x, ss1.x, ee1.x), 0.f));
                    cm[5] = fmaxf(cm[5], fmaxf(fmaf(ac[ii][5] + bb1.y, ss1.y, ee1.y), 0.f));
                    cm[6] = fmaxf(cm[6], fmaxf(fmaf(ac[ii][6] + bb1.z, ss1.z, ee1.z), 0.f));
                    cm[7] = fmaxf(cm[7], fmaxf(fmaf(ac[ii][7] + bb1.w, ss1.w, ee1.w), 0.f));
                }
#pragma unroll
                for (int j = 0; j < 8; j++)
                    atomicMax(&outb[gg * 128 + q0 + j], __float_as_int(cm[j]));
            }
            QBAR(q);

            // write out[b][o][m0..m0+3]
            {
                int o = qtid;
                float4 v;
                v.x = __int_as_float(outb[0 * 128 + o]);
                v.y = __int_as_float(outb[1 * 128 + o]);
                v.z = __int_as_float(outb[2 * 128 + o]);
                v.w = __int_as_float(outb[3 * 128 + o]);
                *(float4*)(out + (b * 128 + o) * MCENT + m0) = v;
            }
            QBAR(q);   // outb/bufA/ticket safe to reuse next item
        }
    }
}

// ---------------------------------------------------------------------------
extern "C" void kernel_launch(void* const* d_in, const int* in_sizes, int n_in,
                              void* d_out, int out_size) {
    const float* points   = (const float*)d_in[0];
    const float* features = (const float*)d_in[1];
    const float* w1  = (const float*)d_in[2];
    const float* b1  = (const float*)d_in[3];
    const float* g1  = (const float*)d_in[4];
    const float* be1 = (const float*)d_in[5];
    const float* w2  = (const float*)d_in[6];
    const float* b2  = (const float*)d_in[7];
    const float* g2  = (const float*)d_in[8];
    const float* be2 = (const float*)d_in[9];
    const float* w3  = (const float*)d_in[10];
    const float* b3  = (const float*)d_in[11];
    const float* g3  = (const float*)d_in[12];
    const float* be3 = (const float*)d_in[13];

    float* cent_out = (float*)d_out;                       // [B][3][M]
    float* out      = cent_out + BATCH * 3 * MCENT;        // [B][128][M]

    cudaFuncSetAttribute(mega_kernel, cudaFuncAttributeMaxDynamicSharedMemorySize, MEGA_SMEM);

    init_kernel<<<1, 32>>>();
    mega_kernel<<<BATCH + 128 + 164, 512, MEGA_SMEM>>>(
        points, features, w1, b1, g1, be1, w2, b2, g2, be2, w3, b3, g3, be3,
        cent_out, out);
}